// round 5
// baseline (speedup 1.0000x reference)
#include <cuda_runtime.h>

// ILRMA: M=N=2, I=1025 freq bins, J=2048 frames, K=8 bases, 5 iterations.
// Layouts (device globals):
//   X,Y : float2 [(i*2+m)*J + j]            (complex interleaved)
//   T   : g_T[n][i*8 + k]
//   V   : g_V[n][j*8 + k]                   (j-major, k contiguous -> float4 pairs)
//   YdR : g_YdR[n][i*J + j]
//   W   : g_W{r,i}[i*4 + n*2 + m]
//   partials: g_p{N,D}[(c*J + j)*16 + n*8 + k]

#define NI 1025
#define NJ 2048
#define NK 8
#define NMF_EPSF 1e-20f
#define IP_EPSF  1e-20f
#define NCH 65
#define ICHUNK 16
#define IJ  (NI*NJ)
#define IMJ (NI*2*NJ)

static __device__ float2 g_X[IMJ];
static __device__ float2 g_Y[IMJ];
static __device__ float  g_YdR[2][IJ];
static __device__ float  g_T[2][NI*NK];
static __device__ float  g_V[2][NJ*NK];
static __device__ float  g_Wr[NI*4];
static __device__ float  g_Wi[NI*4];
static __device__ float  g_pN[NCH*NJ*16];
static __device__ float  g_pD[NCH*NJ*16];

__device__ __forceinline__ float warp_sum(float v) {
#pragma unroll
    for (int o = 16; o > 0; o >>= 1) v += __shfl_down_sync(0xffffffffu, v, o);
    return v;
}

// ---------------------------------------------------------------------------
// Init: T/V de-interleave, W = identity
// ---------------------------------------------------------------------------
__global__ void k_init_tvw(const float* __restrict__ T0, const float* __restrict__ V0) {
    int idx = blockIdx.x * 256 + threadIdx.x;
    if (idx < 16400) {                       // T: (I,K,N) -> [n][i*8+k]
        int n = idx / 8200, r = idx % 8200;
        g_T[n][r] = T0[r * 2 + n];
    } else if (idx < 16400 + 32768) {        // V: (K,J,N) -> [n][j*8+k]
        int v = idx - 16400;
        int n = v / 16384, r = v % 16384;    // r = k*J + j
        int k = r / NJ, j = r % NJ;
        g_V[n][j * 8 + k] = V0[r * 2 + n];
    } else if (idx < 16400 + 32768 + 4100) { // W = eye(2) per i
        int w = idx - 49168;
        int q = w & 3;
        g_Wr[w] = ((q >> 1) == (q & 1)) ? 1.f : 0.f;
        g_Wi[w] = 0.f;
    }
}

// ---------------------------------------------------------------------------
// Init: transpose X (M,J,I,2) -> g_X[(i*2+m)*J+j]; Y0 = Xc (W0 = eye)
// ---------------------------------------------------------------------------
__global__ void k_init_x(const float2* __restrict__ X) {
    __shared__ float2 tile[32][33];
    int m = blockIdx.z;
    int i0 = blockIdx.x * 32, j0 = blockIdx.y * 32;
    int tx = threadIdx.x, ty = threadIdx.y;
#pragma unroll
    for (int r = 0; r < 4; r++) {
        int jj = j0 + ty + r * 8;
        int ii = i0 + tx;
        if (ii < NI) tile[ty + r * 8][tx] = X[(m * NJ + jj) * NI + ii];
    }
    __syncthreads();
#pragma unroll
    for (int r = 0; r < 4; r++) {
        int ii = i0 + ty + r * 8;
        int jj = j0 + tx;
        if (ii < NI) {
            float2 v = tile[tx][ty + r * 8];
            int o = (ii * 2 + m) * NJ + jj;
            g_X[o] = v; g_Y[o] = v;
        }
    }
}

// ---------------------------------------------------------------------------
// NMF T-update, both sources fused. One 128-thread block per frequency bin.
// ---------------------------------------------------------------------------
__global__ void __launch_bounds__(128, 8) k_nmf_t() {
    int i = blockIdx.x;
    int tid = threadIdx.x;
    __shared__ float sT[2][NK];
    if (tid < 16) sT[tid >> 3][tid & 7] = g_T[tid >> 3][i * NK + (tid & 7)];
    __syncthreads();

    float aN[2][NK], aD[2][NK];
#pragma unroll
    for (int n = 0; n < 2; n++)
#pragma unroll
        for (int k = 0; k < NK; k++) { aN[n][k] = 0.f; aD[n][k] = 0.f; }

    for (int j = tid; j < NJ; j += 128) {
#pragma unroll
        for (int n = 0; n < 2; n++) {
            float4 v0 = *(const float4*)&g_V[n][j * 8];
            float4 v1 = *(const float4*)&g_V[n][j * 8 + 4];
            float v[NK] = {v0.x, v0.y, v0.z, v0.w, v1.x, v1.y, v1.z, v1.w};
            float R = 0.f;
#pragma unroll
            for (int k = 0; k < NK; k++) R = fmaf(sT[n][k], v[k], R);
            float2 y = __ldcg(&g_Y[(i * 2 + n) * NJ + j]);
            float p = y.x * y.x + y.y * y.y;
            float m = fabsf(R);
            float ydr = __fdividef(p, m * m + NMF_EPSF);
            float rd  = __fdividef(1.f, m + NMF_EPSF);
            __stcg(&g_YdR[n][i * NJ + j], ydr);
#pragma unroll
            for (int k = 0; k < NK; k++) {
                aN[n][k] = fmaf(ydr, v[k], aN[n][k]);
                aD[n][k] = fmaf(rd, v[k], aD[n][k]);
            }
        }
    }

    __shared__ float rbuf[4][32];
    int warp = tid >> 5, lane = tid & 31;
#pragma unroll
    for (int n = 0; n < 2; n++)
#pragma unroll
        for (int k = 0; k < NK; k++) {
            float sn = warp_sum(aN[n][k]);
            float sd = warp_sum(aD[n][k]);
            if (lane == 0) { rbuf[warp][n * 16 + k] = sn; rbuf[warp][n * 16 + 8 + k] = sd; }
        }
    __syncthreads();
    __shared__ float fin[32];
    if (tid < 32) {
        float s = rbuf[0][tid] + rbuf[1][tid] + rbuf[2][tid] + rbuf[3][tid];
        fin[tid] = s;
    }
    __syncthreads();
    if (tid < 16) {
        int n = tid >> 3, k = tid & 7;
        float num = fin[n * 16 + k], den = fin[n * 16 + 8 + k];
        g_T[n][i * NK + k] = sT[n][k] * sqrtf(__fdividef(num, den + NMF_EPSF));
    }
}

// ---------------------------------------------------------------------------
// NMF V-update partial sums. Grid (J/256, NCH). __launch_bounds__(256,4)
// caps registers at 64 so all 520 blocks fit in ONE wave (4 blocks/SM x 148).
// ---------------------------------------------------------------------------
__global__ void __launch_bounds__(256, 4) k_nmf_v_part() {
    int j = blockIdx.x * 256 + threadIdx.x;
    int c = blockIdx.y;
    int i0 = c * ICHUNK;
    int i1 = i0 + ICHUNK; if (i1 > NI) i1 = NI;

    __shared__ float sT[ICHUNK][16];
    int cnt = (i1 - i0) * 16;
    for (int t = threadIdx.x; t < cnt; t += 256) {
        int ii = t >> 4, q = t & 15;
        sT[ii][q] = g_T[q >> 3][(i0 + ii) * NK + (q & 7)];
    }
    __syncthreads();

    float v[2][NK];
#pragma unroll
    for (int n = 0; n < 2; n++) {
        float4 v0 = *(const float4*)&g_V[n][j * 8];
        float4 v1 = *(const float4*)&g_V[n][j * 8 + 4];
        v[n][0] = v0.x; v[n][1] = v0.y; v[n][2] = v0.z; v[n][3] = v0.w;
        v[n][4] = v1.x; v[n][5] = v1.y; v[n][6] = v1.z; v[n][7] = v1.w;
    }

    float aN[2][NK], aD[2][NK];
#pragma unroll
    for (int n = 0; n < 2; n++)
#pragma unroll
        for (int k = 0; k < NK; k++) { aN[n][k] = 0.f; aD[n][k] = 0.f; }

#pragma unroll 4
    for (int i = i0; i < i1; i++) {
        int li = i - i0;
#pragma unroll
        for (int n = 0; n < 2; n++) {
            float R = 0.f;
#pragma unroll
            for (int k = 0; k < NK; k++) R = fmaf(sT[li][n * 8 + k], v[n][k], R);
            float rd2 = __fdividef(1.f, fabsf(R) + NMF_EPSF);
            float ydr = __ldcg(&g_YdR[n][i * NJ + j]);
#pragma unroll
            for (int k = 0; k < NK; k++) {
                aN[n][k] = fmaf(sT[li][n * 8 + k], ydr, aN[n][k]);
                aD[n][k] = fmaf(sT[li][n * 8 + k], rd2, aD[n][k]);
            }
        }
    }

    int base = (c * NJ + j) * 16;
    *(float4*)&g_pN[base + 0]  = make_float4(aN[0][0], aN[0][1], aN[0][2], aN[0][3]);
    *(float4*)&g_pN[base + 4]  = make_float4(aN[0][4], aN[0][5], aN[0][6], aN[0][7]);
    *(float4*)&g_pN[base + 8]  = make_float4(aN[1][0], aN[1][1], aN[1][2], aN[1][3]);
    *(float4*)&g_pN[base + 12] = make_float4(aN[1][4], aN[1][5], aN[1][6], aN[1][7]);
    *(float4*)&g_pD[base + 0]  = make_float4(aD[0][0], aD[0][1], aD[0][2], aD[0][3]);
    *(float4*)&g_pD[base + 4]  = make_float4(aD[0][4], aD[0][5], aD[0][6], aD[0][7]);
    *(float4*)&g_pD[base + 8]  = make_float4(aD[1][0], aD[1][1], aD[1][2], aD[1][3]);
    *(float4*)&g_pD[base + 12] = make_float4(aD[1][4], aD[1][5], aD[1][6], aD[1][7]);
}

// ---------------------------------------------------------------------------
// NMF V-update reduce: one thread per (j, n, k); V *= sqrt(num/(den+eps))
// ---------------------------------------------------------------------------
__global__ void __launch_bounds__(256) k_nmf_v_red() {
    int idx = blockIdx.x * 256 + threadIdx.x;   // 32768 = J*16
    int j = idx >> 4, q = idx & 15;
    float sn = 0.f, sd = 0.f;
#pragma unroll 5
    for (int c = 0; c < NCH; c++) {
        sn += g_pN[(c * NJ + j) * 16 + q];
        sd += g_pD[(c * NJ + j) * 16 + q];
    }
    int n = q >> 3, k = q & 7;
    g_V[n][j * 8 + k] *= sqrtf(__fdividef(sn, sd + NMF_EPSF));
}

// ---------------------------------------------------------------------------
// Fused IP update (both sources) + Y = W@Xc. One 128-thread block per i.
// No X smem cache: pass 2 re-reads X from L2 (hot). Single wave on chip.
// ---------------------------------------------------------------------------
__global__ void __launch_bounds__(128, 8) k_ip_y() {
    int i = blockIdx.x;
    int tid = threadIdx.x;
    __shared__ float sT[2][NK];
    __shared__ float sW[8];
    if (tid < 16) sT[tid >> 3][tid & 7] = g_T[tid >> 3][i * NK + (tid & 7)];
    __syncthreads();

    float acc[8]; // n*4 + {d00, d11, d01r, d01i}
#pragma unroll
    for (int q = 0; q < 8; q++) acc[q] = 0.f;

    for (int j = tid; j < NJ; j += 128) {
        float2 x0 = __ldcg(&g_X[(i * 2 + 0) * NJ + j]);
        float2 x1 = __ldcg(&g_X[(i * 2 + 1) * NJ + j]);
        float p0 = x0.x * x0.x + x0.y * x0.y;
        float p1 = x1.x * x1.x + x1.y * x1.y;
        float cr = x0.x * x1.x + x0.y * x1.y;
        float ci = x0.y * x1.x - x0.x * x1.y;
#pragma unroll
        for (int n = 0; n < 2; n++) {
            float4 v0 = *(const float4*)&g_V[n][j * 8];
            float4 v1 = *(const float4*)&g_V[n][j * 8 + 4];
            float R = sT[n][0] * v0.x + sT[n][1] * v0.y + sT[n][2] * v0.z + sT[n][3] * v0.w
                    + sT[n][4] * v1.x + sT[n][5] * v1.y + sT[n][6] * v1.z + sT[n][7] * v1.w;
            float w = __fdividef(1.f, R + IP_EPSF);
            acc[n * 4 + 0] = fmaf(w, p0, acc[n * 4 + 0]);
            acc[n * 4 + 1] = fmaf(w, p1, acc[n * 4 + 1]);
            acc[n * 4 + 2] = fmaf(w, cr, acc[n * 4 + 2]);
            acc[n * 4 + 3] = fmaf(w, ci, acc[n * 4 + 3]);
        }
    }

    __shared__ float rb[4][8];
    int warp = tid >> 5, lane = tid & 31;
#pragma unroll
    for (int q = 0; q < 8; q++) {
        float s = warp_sum(acc[q]);
        if (lane == 0) rb[warp][q] = s;
    }
    __syncthreads();
    __shared__ float sD[8];
    if (tid < 8) sD[tid] = rb[0][tid] + rb[1][tid] + rb[2][tid] + rb[3][tid];
    __syncthreads();

    if (tid == 0) {
        float wr[2][2], wi[2][2];
#pragma unroll
        for (int q = 0; q < 4; q++) { wr[q >> 1][q & 1] = g_Wr[i * 4 + q]; wi[q >> 1][q & 1] = g_Wi[i * 4 + q]; }
        const float invJ = 1.f / (float)NJ;
#pragma unroll
        for (int n = 0; n < 2; n++) {
            float D00 = sD[n * 4 + 0] * invJ + IP_EPSF;
            float D11 = sD[n * 4 + 1] * invJ + IP_EPSF;
            float Dr  = sD[n * 4 + 2] * invJ;
            float Di  = sD[n * 4 + 3] * invJ;
            float A00r = wr[0][0] * D00 + wr[0][1] * Dr + wi[0][1] * Di;
            float A00i = wi[0][0] * D00 + wi[0][1] * Dr - wr[0][1] * Di;
            float A01r = wr[0][0] * Dr - wi[0][0] * Di + wr[0][1] * D11;
            float A01i = wi[0][0] * Dr + wr[0][0] * Di + wi[0][1] * D11;
            float A10r = wr[1][0] * D00 + wr[1][1] * Dr + wi[1][1] * Di;
            float A10i = wi[1][0] * D00 + wi[1][1] * Dr - wr[1][1] * Di;
            float A11r = wr[1][0] * Dr - wi[1][0] * Di + wr[1][1] * D11;
            float A11i = wi[1][0] * Dr + wr[1][0] * Di + wi[1][1] * D11;
            float detr = A00r * A11r - A00i * A11i - (A01r * A10r - A01i * A10i);
            float deti = A00r * A11i + A00i * A11r - (A01r * A10i + A01i * A10r);
            float nb0r, nb0i, nb1r, nb1i;
            if (n == 0) { nb0r = A11r; nb0i = A11i; nb1r = -A10r; nb1i = -A10i; }
            else        { nb0r = -A01r; nb0i = -A01i; nb1r = A00r; nb1i = A00i; }
            float inv = 1.f / (detr * detr + deti * deti);
            float b0r = (nb0r * detr + nb0i * deti) * inv;
            float b0i = (nb0i * detr - nb0r * deti) * inv;
            float b1r = (nb1r * detr + nb1i * deti) * inv;
            float b1i = (nb1i * detr - nb1r * deti) * inv;
            float Db0r = D00 * b0r + Dr * b1r - Di * b1i;
            float Db0i = D00 * b0i + Dr * b1i + Di * b1r;
            float Db1r = Dr * b0r + Di * b0i + D11 * b1r;
            float Db1i = Dr * b0i - Di * b0r + D11 * b1i;
            float e = b0r * Db0r + b0i * Db0i + b1r * Db1r + b1i * Db1i;
            float s = 1.f / sqrtf(e + IP_EPSF);
            wr[n][0] = b0r * s; wi[n][0] = -b0i * s;
            wr[n][1] = b1r * s; wi[n][1] = -b1i * s;
        }
#pragma unroll
        for (int q = 0; q < 4; q++) {
            g_Wr[i * 4 + q] = wr[q >> 1][q & 1];
            g_Wi[i * 4 + q] = wi[q >> 1][q & 1];
            sW[q] = wr[q >> 1][q & 1];
            sW[4 + q] = wi[q >> 1][q & 1];
        }
    }
    __syncthreads();

    float w00r = sW[0], w01r = sW[1], w10r = sW[2], w11r = sW[3];
    float w00i = sW[4], w01i = sW[5], w10i = sW[6], w11i = sW[7];
    for (int j = tid; j < NJ; j += 128) {
        float2 x0 = __ldcg(&g_X[(i * 2 + 0) * NJ + j]);
        float2 x1 = __ldcg(&g_X[(i * 2 + 1) * NJ + j]);
        float2 y0, y1;
        y0.x = w00r * x0.x - w00i * x0.y + w01r * x1.x - w01i * x1.y;
        y0.y = w00r * x0.y + w00i * x0.x + w01r * x1.y + w01i * x1.x;
        y1.x = w10r * x0.x - w10i * x0.y + w11r * x1.x - w11i * x1.y;
        y1.y = w10r * x0.y + w10i * x0.x + w11r * x1.y + w11i * x1.x;
        __stcg(&g_Y[(i * 2 + 0) * NJ + j], y0);
        __stcg(&g_Y[(i * 2 + 1) * NJ + j], y1);
    }
}

// ---------------------------------------------------------------------------
// Output: Y [i][n][j] -> out (N, J, I, 2), tiled i<->j transpose
// ---------------------------------------------------------------------------
__global__ void k_out(float2* __restrict__ out) {
    __shared__ float2 tile[32][33];
    int n = blockIdx.z;
    int i0 = blockIdx.x * 32, j0 = blockIdx.y * 32;
    int tx = threadIdx.x, ty = threadIdx.y;
#pragma unroll
    for (int r = 0; r < 4; r++) {
        int ii = i0 + ty + r * 8;
        int jj = j0 + tx;
        if (ii < NI) tile[ty + r * 8][tx] = g_Y[(ii * 2 + n) * NJ + jj];
    }
    __syncthreads();
#pragma unroll
    for (int r = 0; r < 4; r++) {
        int ii = i0 + tx;
        int jj = j0 + ty + r * 8;
        if (ii < NI) out[(n * NJ + jj) * NI + ii] = tile[tx][ty + r * 8];
    }
}

extern "C" void kernel_launch(void* const* d_in, const int* in_sizes, int n_in,
                              void* d_out, int out_size) {
    const float* X  = (const float*)d_in[0];
    const float* T0 = (const float*)d_in[1];
    const float* V0 = (const float*)d_in[2];

    dim3 b32(32, 8);
    k_init_tvw<<<209, 256>>>(T0, V0);
    k_init_x<<<dim3(33, 64, 2), b32>>>((const float2*)X);

    for (int it = 0; it < 5; it++) {
        k_nmf_t<<<NI, 128>>>();
        k_nmf_v_part<<<dim3(NJ / 256, NCH), 256>>>();
        k_nmf_v_red<<<NJ * 16 / 256, 256>>>();
        k_ip_y<<<NI, 128>>>();
    }

    k_out<<<dim3(33, 64, 2), b32>>>((float2*)d_out);
}

// round 12
// speedup vs baseline: 1.2017x; 1.2017x over previous
#include <cuda_runtime.h>

// ILRMA: M=N=2, I=1025 freq bins, J=2048 frames, K=8 bases, 5 iterations.
// Layouts (device globals):
//   X,Y : float2 [(i*2+m)*J + j]            (complex interleaved)
//   T   : g_T[n][i*8 + k]
//   V   : g_V[n][j*8 + k]                   (j-major, k contiguous -> float4 pairs)
//   YdR : g_YdR[n][i*J + j]
//   W   : g_W{r,i}[i*4 + n*2 + m]
//   partials: g_p{N,D}[(c*J + j)*16 + n*8 + k]
// R9: identical intent to R7 submission (infra retry). Single delta vs the
// measured 351.5us kernel: NCH 65->55 so k_nmf_v_part's grid (440 blocks)
// fits exactly one wave at 3 blocks/SM x 148 SMs with its natural 80 regs.

#define NI 1025
#define NJ 2048
#define NK 8
#define NMF_EPSF 1e-20f
#define IP_EPSF  1e-20f
#define NCH 55
#define ICHUNK 19
#define IJ  (NI*NJ)
#define IMJ (NI*2*NJ)

static __device__ float2 g_X[IMJ];
static __device__ float2 g_Y[IMJ];
static __device__ float  g_YdR[2][IJ];
static __device__ float  g_T[2][NI*NK];
static __device__ float  g_V[2][NJ*NK];
static __device__ float  g_Wr[NI*4];
static __device__ float  g_Wi[NI*4];
static __device__ float  g_pN[NCH*NJ*16];
static __device__ float  g_pD[NCH*NJ*16];

__device__ __forceinline__ float warp_sum(float v) {
#pragma unroll
    for (int o = 16; o > 0; o >>= 1) v += __shfl_down_sync(0xffffffffu, v, o);
    return v;
}

// ---------------------------------------------------------------------------
// Init: T/V de-interleave, W = identity
// ---------------------------------------------------------------------------
__global__ void k_init_tvw(const float* __restrict__ T0, const float* __restrict__ V0) {
    int idx = blockIdx.x * 256 + threadIdx.x;
    if (idx < 16400) {                       // T: (I,K,N) -> [n][i*8+k]
        int n = idx / 8200, r = idx % 8200;
        g_T[n][r] = T0[r * 2 + n];
    } else if (idx < 16400 + 32768) {        // V: (K,J,N) -> [n][j*8+k]
        int v = idx - 16400;
        int n = v / 16384, r = v % 16384;    // r = k*J + j
        int k = r / NJ, j = r % NJ;
        g_V[n][j * 8 + k] = V0[r * 2 + n];
    } else if (idx < 16400 + 32768 + 4100) { // W = eye(2) per i
        int w = idx - 49168;
        int q = w & 3;
        g_Wr[w] = ((q >> 1) == (q & 1)) ? 1.f : 0.f;
        g_Wi[w] = 0.f;
    }
}

// ---------------------------------------------------------------------------
// Init: transpose X (M,J,I,2) -> g_X[(i*2+m)*J+j]; Y0 = Xc (W0 = eye)
// ---------------------------------------------------------------------------
__global__ void k_init_x(const float2* __restrict__ X) {
    __shared__ float2 tile[32][33];
    int m = blockIdx.z;
    int i0 = blockIdx.x * 32, j0 = blockIdx.y * 32;
    int tx = threadIdx.x, ty = threadIdx.y;
#pragma unroll
    for (int r = 0; r < 4; r++) {
        int jj = j0 + ty + r * 8;
        int ii = i0 + tx;
        if (ii < NI) tile[ty + r * 8][tx] = X[(m * NJ + jj) * NI + ii];
    }
    __syncthreads();
#pragma unroll
    for (int r = 0; r < 4; r++) {
        int ii = i0 + ty + r * 8;
        int jj = j0 + tx;
        if (ii < NI) {
            float2 v = tile[tx][ty + r * 8];
            int o = (ii * 2 + m) * NJ + jj;
            g_X[o] = v; g_Y[o] = v;
        }
    }
}

// ---------------------------------------------------------------------------
// NMF T-update, both sources fused. One 256-thread block per frequency bin.
// ---------------------------------------------------------------------------
__global__ void __launch_bounds__(256) k_nmf_t() {
    int i = blockIdx.x;
    int tid = threadIdx.x;
    __shared__ float sT[2][NK];
    if (tid < 16) sT[tid >> 3][tid & 7] = g_T[tid >> 3][i * NK + (tid & 7)];
    __syncthreads();

    float aN[2][NK], aD[2][NK];
#pragma unroll
    for (int n = 0; n < 2; n++)
#pragma unroll
        for (int k = 0; k < NK; k++) { aN[n][k] = 0.f; aD[n][k] = 0.f; }

    for (int j = tid; j < NJ; j += 256) {
#pragma unroll
        for (int n = 0; n < 2; n++) {
            float4 v0 = *(const float4*)&g_V[n][j * 8];
            float4 v1 = *(const float4*)&g_V[n][j * 8 + 4];
            float v[NK] = {v0.x, v0.y, v0.z, v0.w, v1.x, v1.y, v1.z, v1.w};
            float R = 0.f;
#pragma unroll
            for (int k = 0; k < NK; k++) R = fmaf(sT[n][k], v[k], R);
            float2 y = __ldcg(&g_Y[(i * 2 + n) * NJ + j]);
            float p = y.x * y.x + y.y * y.y;
            float m = fabsf(R);
            float ydr = __fdividef(p, m * m + NMF_EPSF);
            float rd  = __fdividef(1.f, m + NMF_EPSF);
            __stcg(&g_YdR[n][i * NJ + j], ydr);
#pragma unroll
            for (int k = 0; k < NK; k++) {
                aN[n][k] = fmaf(ydr, v[k], aN[n][k]);
                aD[n][k] = fmaf(rd, v[k], aD[n][k]);
            }
        }
    }

    __shared__ float rbuf[8][32];
    int warp = tid >> 5, lane = tid & 31;
#pragma unroll
    for (int n = 0; n < 2; n++)
#pragma unroll
        for (int k = 0; k < NK; k++) {
            float sn = warp_sum(aN[n][k]);
            float sd = warp_sum(aD[n][k]);
            if (lane == 0) { rbuf[warp][n * 16 + k] = sn; rbuf[warp][n * 16 + 8 + k] = sd; }
        }
    __syncthreads();
    __shared__ float fin[32];
    if (tid < 32) {
        float s = 0.f;
#pragma unroll
        for (int w = 0; w < 8; w++) s += rbuf[w][tid];
        fin[tid] = s;
    }
    __syncthreads();
    if (tid < 16) {
        int n = tid >> 3, k = tid & 7;
        float num = fin[n * 16 + k], den = fin[n * 16 + 8 + k];
        g_T[n][i * NK + k] = sT[n][k] * sqrtf(__fdividef(num, den + NMF_EPSF));
    }
}

// ---------------------------------------------------------------------------
// NMF V-update partial sums. Grid (J/256, NCH) = 8*55 = 440 blocks:
// one full wave at 3 blocks/SM (80 regs) on 148 SMs. No reg cap (spills
// measured worse than the wave tail in R4).
// ---------------------------------------------------------------------------
__global__ void __launch_bounds__(256) k_nmf_v_part() {
    int j = blockIdx.x * 256 + threadIdx.x;
    int c = blockIdx.y;
    int i0 = c * ICHUNK;
    int i1 = i0 + ICHUNK; if (i1 > NI) i1 = NI;

    __shared__ float sT[ICHUNK][16];
    int cnt = (i1 - i0) * 16;
    for (int t = threadIdx.x; t < cnt; t += 256) {
        int ii = t >> 4, q = t & 15;
        sT[ii][q] = g_T[q >> 3][(i0 + ii) * NK + (q & 7)];
    }
    __syncthreads();

    float v[2][NK];
#pragma unroll
    for (int n = 0; n < 2; n++) {
        float4 v0 = *(const float4*)&g_V[n][j * 8];
        float4 v1 = *(const float4*)&g_V[n][j * 8 + 4];
        v[n][0] = v0.x; v[n][1] = v0.y; v[n][2] = v0.z; v[n][3] = v0.w;
        v[n][4] = v1.x; v[n][5] = v1.y; v[n][6] = v1.z; v[n][7] = v1.w;
    }

    float aN[2][NK], aD[2][NK];
#pragma unroll
    for (int n = 0; n < 2; n++)
#pragma unroll
        for (int k = 0; k < NK; k++) { aN[n][k] = 0.f; aD[n][k] = 0.f; }

#pragma unroll 4
    for (int i = i0; i < i1; i++) {
        int li = i - i0;
#pragma unroll
        for (int n = 0; n < 2; n++) {
            float R = 0.f;
#pragma unroll
            for (int k = 0; k < NK; k++) R = fmaf(sT[li][n * 8 + k], v[n][k], R);
            float rd2 = __fdividef(1.f, fabsf(R) + NMF_EPSF);
            float ydr = __ldcg(&g_YdR[n][i * NJ + j]);
#pragma unroll
            for (int k = 0; k < NK; k++) {
                aN[n][k] = fmaf(sT[li][n * 8 + k], ydr, aN[n][k]);
                aD[n][k] = fmaf(sT[li][n * 8 + k], rd2, aD[n][k]);
            }
        }
    }

    int base = (c * NJ + j) * 16;
    *(float4*)&g_pN[base + 0]  = make_float4(aN[0][0], aN[0][1], aN[0][2], aN[0][3]);
    *(float4*)&g_pN[base + 4]  = make_float4(aN[0][4], aN[0][5], aN[0][6], aN[0][7]);
    *(float4*)&g_pN[base + 8]  = make_float4(aN[1][0], aN[1][1], aN[1][2], aN[1][3]);
    *(float4*)&g_pN[base + 12] = make_float4(aN[1][4], aN[1][5], aN[1][6], aN[1][7]);
    *(float4*)&g_pD[base + 0]  = make_float4(aD[0][0], aD[0][1], aD[0][2], aD[0][3]);
    *(float4*)&g_pD[base + 4]  = make_float4(aD[0][4], aD[0][5], aD[0][6], aD[0][7]);
    *(float4*)&g_pD[base + 8]  = make_float4(aD[1][0], aD[1][1], aD[1][2], aD[1][3]);
    *(float4*)&g_pD[base + 12] = make_float4(aD[1][4], aD[1][5], aD[1][6], aD[1][7]);
}

// ---------------------------------------------------------------------------
// NMF V-update reduce: one thread per (j, n, k); V *= sqrt(num/(den+eps))
// ---------------------------------------------------------------------------
__global__ void __launch_bounds__(256) k_nmf_v_red() {
    int idx = blockIdx.x * 256 + threadIdx.x;   // 32768 = J*16
    int j = idx >> 4, q = idx & 15;
    float sn = 0.f, sd = 0.f;
#pragma unroll 5
    for (int c = 0; c < NCH; c++) {
        sn += g_pN[(c * NJ + j) * 16 + q];
        sd += g_pD[(c * NJ + j) * 16 + q];
    }
    int n = q >> 3, k = q & 7;
    g_V[n][j * 8 + k] *= sqrtf(__fdividef(sn, sd + NMF_EPSF));
}

// ---------------------------------------------------------------------------
// Fused IP update (both sources) + Y = W@Xc. One 256-thread block per i.
// X row cached in smem for pass 2 (measured-good R3 configuration).
// ---------------------------------------------------------------------------
__global__ void __launch_bounds__(256) k_ip_y() {
    int i = blockIdx.x;
    int tid = threadIdx.x;
    __shared__ float2 sX[2][NJ];
    __shared__ float sT[2][NK];
    __shared__ float sW[8];
    if (tid < 16) sT[tid >> 3][tid & 7] = g_T[tid >> 3][i * NK + (tid & 7)];
    __syncthreads();

    float acc[8]; // n*4 + {d00, d11, d01r, d01i}
#pragma unroll
    for (int q = 0; q < 8; q++) acc[q] = 0.f;

    for (int j = tid; j < NJ; j += 256) {
        float2 x0 = __ldcg(&g_X[(i * 2 + 0) * NJ + j]);
        float2 x1 = __ldcg(&g_X[(i * 2 + 1) * NJ + j]);
        sX[0][j] = x0; sX[1][j] = x1;
        float p0 = x0.x * x0.x + x0.y * x0.y;
        float p1 = x1.x * x1.x + x1.y * x1.y;
        float cr = x0.x * x1.x + x0.y * x1.y;
        float ci = x0.y * x1.x - x0.x * x1.y;
#pragma unroll
        for (int n = 0; n < 2; n++) {
            float4 v0 = *(const float4*)&g_V[n][j * 8];
            float4 v1 = *(const float4*)&g_V[n][j * 8 + 4];
            float R = sT[n][0] * v0.x + sT[n][1] * v0.y + sT[n][2] * v0.z + sT[n][3] * v0.w
                    + sT[n][4] * v1.x + sT[n][5] * v1.y + sT[n][6] * v1.z + sT[n][7] * v1.w;
            float w = __fdividef(1.f, R + IP_EPSF);
            acc[n * 4 + 0] = fmaf(w, p0, acc[n * 4 + 0]);
            acc[n * 4 + 1] = fmaf(w, p1, acc[n * 4 + 1]);
            acc[n * 4 + 2] = fmaf(w, cr, acc[n * 4 + 2]);
            acc[n * 4 + 3] = fmaf(w, ci, acc[n * 4 + 3]);
        }
    }

    __shared__ float rb[8][8];
    int warp = tid >> 5, lane = tid & 31;
#pragma unroll
    for (int q = 0; q < 8; q++) {
        float s = warp_sum(acc[q]);
        if (lane == 0) rb[warp][q] = s;
    }
    __syncthreads();
    __shared__ float sD[8];
    if (tid < 8) {
        float s = 0.f;
#pragma unroll
        for (int w = 0; w < 8; w++) s += rb[w][tid];
        sD[tid] = s;
    }
    __syncthreads();

    if (tid == 0) {
        float wr[2][2], wi[2][2];
#pragma unroll
        for (int q = 0; q < 4; q++) { wr[q >> 1][q & 1] = g_Wr[i * 4 + q]; wi[q >> 1][q & 1] = g_Wi[i * 4 + q]; }
        const float invJ = 1.f / (float)NJ;
#pragma unroll
        for (int n = 0; n < 2; n++) {
            float D00 = sD[n * 4 + 0] * invJ + IP_EPSF;
            float D11 = sD[n * 4 + 1] * invJ + IP_EPSF;
            float Dr  = sD[n * 4 + 2] * invJ;
            float Di  = sD[n * 4 + 3] * invJ;
            float A00r = wr[0][0] * D00 + wr[0][1] * Dr + wi[0][1] * Di;
            float A00i = wi[0][0] * D00 + wi[0][1] * Dr - wr[0][1] * Di;
            float A01r = wr[0][0] * Dr - wi[0][0] * Di + wr[0][1] * D11;
            float A01i = wi[0][0] * Dr + wr[0][0] * Di + wi[0][1] * D11;
            float A10r = wr[1][0] * D00 + wr[1][1] * Dr + wi[1][1] * Di;
            float A10i = wi[1][0] * D00 + wi[1][1] * Dr - wr[1][1] * Di;
            float A11r = wr[1][0] * Dr - wi[1][0] * Di + wr[1][1] * D11;
            float A11i = wi[1][0] * Dr + wr[1][0] * Di + wi[1][1] * D11;
            float detr = A00r * A11r - A00i * A11i - (A01r * A10r - A01i * A10i);
            float deti = A00r * A11i + A00i * A11r - (A01r * A10i + A01i * A10r);
            float nb0r, nb0i, nb1r, nb1i;
            if (n == 0) { nb0r = A11r; nb0i = A11i; nb1r = -A10r; nb1i = -A10i; }
            else        { nb0r = -A01r; nb0i = -A01i; nb1r = A00r; nb1i = A00i; }
            float inv = 1.f / (detr * detr + deti * deti);
            float b0r = (nb0r * detr + nb0i * deti) * inv;
            float b0i = (nb0i * detr - nb0r * deti) * inv;
            float b1r = (nb1r * detr + nb1i * deti) * inv;
            float b1i = (nb1i * detr - nb1r * deti) * inv;
            float Db0r = D00 * b0r + Dr * b1r - Di * b1i;
            float Db0i = D00 * b0i + Dr * b1i + Di * b1r;
            float Db1r = Dr * b0r + Di * b0i + D11 * b1r;
            float Db1i = Dr * b0i - Di * b0r + D11 * b1i;
            float e = b0r * Db0r + b0i * Db0i + b1r * Db1r + b1i * Db1i;
            float s = 1.f / sqrtf(e + IP_EPSF);
            wr[n][0] = b0r * s; wi[n][0] = -b0i * s;
            wr[n][1] = b1r * s; wi[n][1] = -b1i * s;
        }
#pragma unroll
        for (int q = 0; q < 4; q++) {
            g_Wr[i * 4 + q] = wr[q >> 1][q & 1];
            g_Wi[i * 4 + q] = wi[q >> 1][q & 1];
            sW[q] = wr[q >> 1][q & 1];
            sW[4 + q] = wi[q >> 1][q & 1];
        }
    }
    __syncthreads();

    float w00r = sW[0], w01r = sW[1], w10r = sW[2], w11r = sW[3];
    float w00i = sW[4], w01i = sW[5], w10i = sW[6], w11i = sW[7];
    for (int j = tid; j < NJ; j += 256) {
        float2 x0 = sX[0][j], x1 = sX[1][j];
        float2 y0, y1;
        y0.x = w00r * x0.x - w00i * x0.y + w01r * x1.x - w01i * x1.y;
        y0.y = w00r * x0.y + w00i * x0.x + w01r * x1.y + w01i * x1.x;
        y1.x = w10r * x0.x - w10i * x0.y + w11r * x1.x - w11i * x1.y;
        y1.y = w10r * x0.y + w10i * x0.x + w11r * x1.y + w11i * x1.x;
        __stcg(&g_Y[(i * 2 + 0) * NJ + j], y0);
        __stcg(&g_Y[(i * 2 + 1) * NJ + j], y1);
    }
}

// ---------------------------------------------------------------------------
// Output: Y [i][n][j] -> out (N, J, I, 2), tiled i<->j transpose
// ---------------------------------------------------------------------------
__global__ void k_out(float2* __restrict__ out) {
    __shared__ float2 tile[32][33];
    int n = blockIdx.z;
    int i0 = blockIdx.x * 32, j0 = blockIdx.y * 32;
    int tx = threadIdx.x, ty = threadIdx.y;
#pragma unroll
    for (int r = 0; r < 4; r++) {
        int ii = i0 + ty + r * 8;
        int jj = j0 + tx;
        if (ii < NI) tile[ty + r * 8][tx] = g_Y[(ii * 2 + n) * NJ + jj];
    }
    __syncthreads();
#pragma unroll
    for (int r = 0; r < 4; r++) {
        int ii = i0 + tx;
        int jj = j0 + ty + r * 8;
        if (ii < NI) out[(n * NJ + jj) * NI + ii] = tile[tx][ty + r * 8];
    }
}

extern "C" void kernel_launch(void* const* d_in, const int* in_sizes, int n_in,
                              void* d_out, int out_size) {
    const float* X  = (const float*)d_in[0];
    const float* T0 = (const float*)d_in[1];
    const float* V0 = (const float*)d_in[2];

    dim3 b32(32, 8);
    k_init_tvw<<<209, 256>>>(T0, V0);
    k_init_x<<<dim3(33, 64, 2), b32>>>((const float2*)X);

    for (int it = 0; it < 5; it++) {
        k_nmf_t<<<NI, 256>>>();
        k_nmf_v_part<<<dim3(NJ / 256, NCH), 256>>>();
        k_nmf_v_red<<<NJ * 16 / 256, 256>>>();
        k_ip_y<<<NI, 256>>>();
    }

    k_out<<<dim3(33, 64, 2), b32>>>((float2*)d_out);
}

// round 15
// speedup vs baseline: 1.2497x; 1.0399x over previous
#include <cuda_runtime.h>

// ILRMA: M=N=2, I=1025 freq bins, J=2048 frames, K=8 bases, 5 iterations.
// Layouts (device globals):
//   X,Y : float2 [(i*2+m)*J + j]            (complex interleaved)
//   T   : g_T[n][i*8 + k]
//   V   : g_V[n][j*8 + k]                   (j-major, k contiguous -> float4 pairs)
//   YdR : g_YdR[n][i*J + j]
//   W   : g_W{r,i}[i*4 + n*2 + m]
//   partials: g_p{N,D}[(c*J + j)*16 + n*8 + k]
// R14 (infra retry of R13, semantics identical):
// (a) v_part batches all ICHUNK YdR loads per n-phase into registers
//     (MLP 19 vs ~8): the R12 profile showed the kernel running exactly at
//     its YdR DRAM-read throughput (1005GB/s = 12.7% of peak), i.e.
//     latency-bound, not bandwidth-bound.
// (b) Y0 = X is implicit: init skips the g_Y store, nmf_t reads g_X on it 0.

#define NI 1025
#define NJ 2048
#define NK 8
#define NMF_EPSF 1e-20f
#define IP_EPSF  1e-20f
#define NCH 55
#define ICHUNK 19
#define IJ  (NI*NJ)
#define IMJ (NI*2*NJ)

static __device__ float2 g_X[IMJ];
static __device__ float2 g_Y[IMJ];
static __device__ float  g_YdR[2][IJ];
static __device__ float  g_T[2][NI*NK];
static __device__ float  g_V[2][NJ*NK];
static __device__ float  g_Wr[NI*4];
static __device__ float  g_Wi[NI*4];
static __device__ float  g_pN[NCH*NJ*16];
static __device__ float  g_pD[NCH*NJ*16];

__device__ __forceinline__ float warp_sum(float v) {
#pragma unroll
    for (int o = 16; o > 0; o >>= 1) v += __shfl_down_sync(0xffffffffu, v, o);
    return v;
}

// ---------------------------------------------------------------------------
// Init: T/V de-interleave, W = identity
// ---------------------------------------------------------------------------
__global__ void k_init_tvw(const float* __restrict__ T0, const float* __restrict__ V0) {
    int idx = blockIdx.x * 256 + threadIdx.x;
    if (idx < 16400) {                       // T: (I,K,N) -> [n][i*8+k]
        int n = idx / 8200, r = idx % 8200;
        g_T[n][r] = T0[r * 2 + n];
    } else if (idx < 16400 + 32768) {        // V: (K,J,N) -> [n][j*8+k]
        int v = idx - 16400;
        int n = v / 16384, r = v % 16384;    // r = k*J + j
        int k = r / NJ, j = r % NJ;
        g_V[n][j * 8 + k] = V0[r * 2 + n];
    } else if (idx < 16400 + 32768 + 4100) { // W = eye(2) per i
        int w = idx - 49168;
        int q = w & 3;
        g_Wr[w] = ((q >> 1) == (q & 1)) ? 1.f : 0.f;
        g_Wi[w] = 0.f;
    }
}

// ---------------------------------------------------------------------------
// Init: transpose X (M,J,I,2) -> g_X[(i*2+m)*J+j]. (Y0 = X handled by flag.)
// ---------------------------------------------------------------------------
__global__ void k_init_x(const float2* __restrict__ X) {
    __shared__ float2 tile[32][33];
    int m = blockIdx.z;
    int i0 = blockIdx.x * 32, j0 = blockIdx.y * 32;
    int tx = threadIdx.x, ty = threadIdx.y;
#pragma unroll
    for (int r = 0; r < 4; r++) {
        int jj = j0 + ty + r * 8;
        int ii = i0 + tx;
        if (ii < NI) tile[ty + r * 8][tx] = X[(m * NJ + jj) * NI + ii];
    }
    __syncthreads();
#pragma unroll
    for (int r = 0; r < 4; r++) {
        int ii = i0 + ty + r * 8;
        int jj = j0 + tx;
        if (ii < NI) g_X[(ii * 2 + m) * NJ + jj] = tile[tx][ty + r * 8];
    }
}

// ---------------------------------------------------------------------------
// NMF T-update, both sources fused. One 256-thread block per frequency bin.
// useX != 0 on iteration 0 (Y0 == X, never materialized).
// ---------------------------------------------------------------------------
__global__ void __launch_bounds__(256) k_nmf_t(int useX) {
    int i = blockIdx.x;
    int tid = threadIdx.x;
    const float2* __restrict__ Ysrc = useX ? g_X : g_Y;
    __shared__ float sT[2][NK];
    if (tid < 16) sT[tid >> 3][tid & 7] = g_T[tid >> 3][i * NK + (tid & 7)];
    __syncthreads();

    float aN[2][NK], aD[2][NK];
#pragma unroll
    for (int n = 0; n < 2; n++)
#pragma unroll
        for (int k = 0; k < NK; k++) { aN[n][k] = 0.f; aD[n][k] = 0.f; }

    for (int j = tid; j < NJ; j += 256) {
#pragma unroll
        for (int n = 0; n < 2; n++) {
            float4 v0 = *(const float4*)&g_V[n][j * 8];
            float4 v1 = *(const float4*)&g_V[n][j * 8 + 4];
            float v[NK] = {v0.x, v0.y, v0.z, v0.w, v1.x, v1.y, v1.z, v1.w};
            float R = 0.f;
#pragma unroll
            for (int k = 0; k < NK; k++) R = fmaf(sT[n][k], v[k], R);
            float2 y = __ldcg(&Ysrc[(i * 2 + n) * NJ + j]);
            float p = y.x * y.x + y.y * y.y;
            float m = fabsf(R);
            float ydr = __fdividef(p, m * m + NMF_EPSF);
            float rd  = __fdividef(1.f, m + NMF_EPSF);
            __stcg(&g_YdR[n][i * NJ + j], ydr);
#pragma unroll
            for (int k = 0; k < NK; k++) {
                aN[n][k] = fmaf(ydr, v[k], aN[n][k]);
                aD[n][k] = fmaf(rd, v[k], aD[n][k]);
            }
        }
    }

    __shared__ float rbuf[8][32];
    int warp = tid >> 5, lane = tid & 31;
#pragma unroll
    for (int n = 0; n < 2; n++)
#pragma unroll
        for (int k = 0; k < NK; k++) {
            float sn = warp_sum(aN[n][k]);
            float sd = warp_sum(aD[n][k]);
            if (lane == 0) { rbuf[warp][n * 16 + k] = sn; rbuf[warp][n * 16 + 8 + k] = sd; }
        }
    __syncthreads();
    __shared__ float fin[32];
    if (tid < 32) {
        float s = 0.f;
#pragma unroll
        for (int w = 0; w < 8; w++) s += rbuf[w][tid];
        fin[tid] = s;
    }
    __syncthreads();
    if (tid < 16) {
        int n = tid >> 3, k = tid & 7;
        float num = fin[n * 16 + k], den = fin[n * 16 + 8 + k];
        g_T[n][i * NK + k] = sT[n][k] * sqrtf(__fdividef(num, den + NMF_EPSF));
    }
}

// ---------------------------------------------------------------------------
// NMF V-update partial sums. Grid (J/256, NCH) = 440 blocks (one full wave).
// Per n-phase, all ICHUNK YdR loads are batched into registers first
// (MLP = 19) before the FMA sweep. Out-of-range i: sT = 0 and ydr = 0 =>
// contributes exactly 0 to every accumulator.
// ---------------------------------------------------------------------------
__global__ void __launch_bounds__(256) k_nmf_v_part() {
    int j = blockIdx.x * 256 + threadIdx.x;
    int c = blockIdx.y;
    int i0 = c * ICHUNK;
    int nvalid = NI - i0; if (nvalid > ICHUNK) nvalid = ICHUNK;

    __shared__ float sT[ICHUNK][16];
    for (int t = threadIdx.x; t < ICHUNK * 16; t += 256) {
        int ii = t >> 4, q = t & 15;
        sT[ii][q] = (ii < nvalid) ? g_T[q >> 3][(i0 + ii) * NK + (q & 7)] : 0.f;
    }
    __syncthreads();

    float aN[2][NK], aD[2][NK];
#pragma unroll
    for (int n = 0; n < 2; n++)
#pragma unroll
        for (int k = 0; k < NK; k++) { aN[n][k] = 0.f; aD[n][k] = 0.f; }

#pragma unroll
    for (int n = 0; n < 2; n++) {
        float4 v0 = *(const float4*)&g_V[n][j * 8];
        float4 v1 = *(const float4*)&g_V[n][j * 8 + 4];
        float v[NK] = {v0.x, v0.y, v0.z, v0.w, v1.x, v1.y, v1.z, v1.w};

        float ydr[ICHUNK];
        const float* base = &g_YdR[n][i0 * NJ + j];
#pragma unroll
        for (int li = 0; li < ICHUNK; li++)
            ydr[li] = (li < nvalid) ? __ldcg(base + li * NJ) : 0.f;

#pragma unroll
        for (int li = 0; li < ICHUNK; li++) {
            float R = 0.f;
#pragma unroll
            for (int k = 0; k < NK; k++) R = fmaf(sT[li][n * 8 + k], v[k], R);
            float rd2 = __fdividef(1.f, fabsf(R) + NMF_EPSF);
#pragma unroll
            for (int k = 0; k < NK; k++) {
                aN[n][k] = fmaf(sT[li][n * 8 + k], ydr[li], aN[n][k]);
                aD[n][k] = fmaf(sT[li][n * 8 + k], rd2, aD[n][k]);
            }
        }
    }

    int pbase = (c * NJ + j) * 16;
    *(float4*)&g_pN[pbase + 0]  = make_float4(aN[0][0], aN[0][1], aN[0][2], aN[0][3]);
    *(float4*)&g_pN[pbase + 4]  = make_float4(aN[0][4], aN[0][5], aN[0][6], aN[0][7]);
    *(float4*)&g_pN[pbase + 8]  = make_float4(aN[1][0], aN[1][1], aN[1][2], aN[1][3]);
    *(float4*)&g_pN[pbase + 12] = make_float4(aN[1][4], aN[1][5], aN[1][6], aN[1][7]);
    *(float4*)&g_pD[pbase + 0]  = make_float4(aD[0][0], aD[0][1], aD[0][2], aD[0][3]);
    *(float4*)&g_pD[pbase + 4]  = make_float4(aD[0][4], aD[0][5], aD[0][6], aD[0][7]);
    *(float4*)&g_pD[pbase + 8]  = make_float4(aD[1][0], aD[1][1], aD[1][2], aD[1][3]);
    *(float4*)&g_pD[pbase + 12] = make_float4(aD[1][4], aD[1][5], aD[1][6], aD[1][7]);
}

// ---------------------------------------------------------------------------
// NMF V-update reduce: one thread per (j, n, k); V *= sqrt(num/(den+eps))
// ---------------------------------------------------------------------------
__global__ void __launch_bounds__(256) k_nmf_v_red() {
    int idx = blockIdx.x * 256 + threadIdx.x;   // 32768 = J*16
    int j = idx >> 4, q = idx & 15;
    float sn = 0.f, sd = 0.f;
#pragma unroll 5
    for (int c = 0; c < NCH; c++) {
        sn += g_pN[(c * NJ + j) * 16 + q];
        sd += g_pD[(c * NJ + j) * 16 + q];
    }
    int n = q >> 3, k = q & 7;
    g_V[n][j * 8 + k] *= sqrtf(__fdividef(sn, sd + NMF_EPSF));
}

// ---------------------------------------------------------------------------
// Fused IP update (both sources) + Y = W@Xc. One 256-thread block per i.
// X row cached in smem for pass 2 (measured-good configuration).
// ---------------------------------------------------------------------------
__global__ void __launch_bounds__(256) k_ip_y() {
    int i = blockIdx.x;
    int tid = threadIdx.x;
    __shared__ float2 sX[2][NJ];
    __shared__ float sT[2][NK];
    __shared__ float sW[8];
    if (tid < 16) sT[tid >> 3][tid & 7] = g_T[tid >> 3][i * NK + (tid & 7)];
    __syncthreads();

    float acc[8]; // n*4 + {d00, d11, d01r, d01i}
#pragma unroll
    for (int q = 0; q < 8; q++) acc[q] = 0.f;

    for (int j = tid; j < NJ; j += 256) {
        float2 x0 = __ldcg(&g_X[(i * 2 + 0) * NJ + j]);
        float2 x1 = __ldcg(&g_X[(i * 2 + 1) * NJ + j]);
        sX[0][j] = x0; sX[1][j] = x1;
        float p0 = x0.x * x0.x + x0.y * x0.y;
        float p1 = x1.x * x1.x + x1.y * x1.y;
        float cr = x0.x * x1.x + x0.y * x1.y;
        float ci = x0.y * x1.x - x0.x * x1.y;
#pragma unroll
        for (int n = 0; n < 2; n++) {
            float4 v0 = *(const float4*)&g_V[n][j * 8];
            float4 v1 = *(const float4*)&g_V[n][j * 8 + 4];
            float R = sT[n][0] * v0.x + sT[n][1] * v0.y + sT[n][2] * v0.z + sT[n][3] * v0.w
                    + sT[n][4] * v1.x + sT[n][5] * v1.y + sT[n][6] * v1.z + sT[n][7] * v1.w;
            float w = __fdividef(1.f, R + IP_EPSF);
            acc[n * 4 + 0] = fmaf(w, p0, acc[n * 4 + 0]);
            acc[n * 4 + 1] = fmaf(w, p1, acc[n * 4 + 1]);
            acc[n * 4 + 2] = fmaf(w, cr, acc[n * 4 + 2]);
            acc[n * 4 + 3] = fmaf(w, ci, acc[n * 4 + 3]);
        }
    }

    __shared__ float rb[8][8];
    int warp = tid >> 5, lane = tid & 31;
#pragma unroll
    for (int q = 0; q < 8; q++) {
        float s = warp_sum(acc[q]);
        if (lane == 0) rb[warp][q] = s;
    }
    __syncthreads();
    __shared__ float sD[8];
    if (tid < 8) {
        float s = 0.f;
#pragma unroll
        for (int w = 0; w < 8; w++) s += rb[w][tid];
        sD[tid] = s;
    }
    __syncthreads();

    if (tid == 0) {
        float wr[2][2], wi[2][2];
#pragma unroll
        for (int q = 0; q < 4; q++) { wr[q >> 1][q & 1] = g_Wr[i * 4 + q]; wi[q >> 1][q & 1] = g_Wi[i * 4 + q]; }
        const float invJ = 1.f / (float)NJ;
#pragma unroll
        for (int n = 0; n < 2; n++) {
            float D00 = sD[n * 4 + 0] * invJ + IP_EPSF;
            float D11 = sD[n * 4 + 1] * invJ + IP_EPSF;
            float Dr  = sD[n * 4 + 2] * invJ;
            float Di  = sD[n * 4 + 3] * invJ;
            float A00r = wr[0][0] * D00 + wr[0][1] * Dr + wi[0][1] * Di;
            float A00i = wi[0][0] * D00 + wi[0][1] * Dr - wr[0][1] * Di;
            float A01r = wr[0][0] * Dr - wi[0][0] * Di + wr[0][1] * D11;
            float A01i = wi[0][0] * Dr + wr[0][0] * Di + wi[0][1] * D11;
            float A10r = wr[1][0] * D00 + wr[1][1] * Dr + wi[1][1] * Di;
            float A10i = wi[1][0] * D00 + wi[1][1] * Dr - wr[1][1] * Di;
            float A11r = wr[1][0] * Dr - wi[1][0] * Di + wr[1][1] * D11;
            float A11i = wi[1][0] * Dr + wr[1][0] * Di + wi[1][1] * D11;
            float detr = A00r * A11r - A00i * A11i - (A01r * A10r - A01i * A10i);
            float deti = A00r * A11i + A00i * A11r - (A01r * A10i + A01i * A10r);
            float nb0r, nb0i, nb1r, nb1i;
            if (n == 0) { nb0r = A11r; nb0i = A11i; nb1r = -A10r; nb1i = -A10i; }
            else        { nb0r = -A01r; nb0i = -A01i; nb1r = A00r; nb1i = A00i; }
            float inv = 1.f / (detr * detr + deti * deti);
            float b0r = (nb0r * detr + nb0i * deti) * inv;
            float b0i = (nb0i * detr - nb0r * deti) * inv;
            float b1r = (nb1r * detr + nb1i * deti) * inv;
            float b1i = (nb1i * detr - nb1r * deti) * inv;
            float Db0r = D00 * b0r + Dr * b1r - Di * b1i;
            float Db0i = D00 * b0i + Dr * b1i + Di * b1r;
            float Db1r = Dr * b0r + Di * b0i + D11 * b1r;
            float Db1i = Dr * b0i - Di * b0r + D11 * b1i;
            float e = b0r * Db0r + b0i * Db0i + b1r * Db1r + b1i * Db1i;
            float s = 1.f / sqrtf(e + IP_EPSF);
            wr[n][0] = b0r * s; wi[n][0] = -b0i * s;
            wr[n][1] = b1r * s; wi[n][1] = -b1i * s;
        }
#pragma unroll
        for (int q = 0; q < 4; q++) {
            g_Wr[i * 4 + q] = wr[q >> 1][q & 1];
            g_Wi[i * 4 + q] = wi[q >> 1][q & 1];
            sW[q] = wr[q >> 1][q & 1];
            sW[4 + q] = wi[q >> 1][q & 1];
        }
    }
    __syncthreads();

    float w00r = sW[0], w01r = sW[1], w10r = sW[2], w11r = sW[3];
    float w00i = sW[4], w01i = sW[5], w10i = sW[6], w11i = sW[7];
    for (int j = tid; j < NJ; j += 256) {
        float2 x0 = sX[0][j], x1 = sX[1][j];
        float2 y0, y1;
        y0.x = w00r * x0.x - w00i * x0.y + w01r * x1.x - w01i * x1.y;
        y0.y = w00r * x0.y + w00i * x0.x + w01r * x1.y + w01i * x1.x;
        y1.x = w10r * x0.x - w10i * x0.y + w11r * x1.x - w11i * x1.y;
        y1.y = w10r * x0.y + w10i * x0.x + w11r * x1.y + w11i * x1.x;
        __stcg(&g_Y[(i * 2 + 0) * NJ + j], y0);
        __stcg(&g_Y[(i * 2 + 1) * NJ + j], y1);
    }
}

// ---------------------------------------------------------------------------
// Output: Y [i][n][j] -> out (N, J, I, 2), tiled i<->j transpose
// ---------------------------------------------------------------------------
__global__ void k_out(float2* __restrict__ out) {
    __shared__ float2 tile[32][33];
    int n = blockIdx.z;
    int i0 = blockIdx.x * 32, j0 = blockIdx.y * 32;
    int tx = threadIdx.x, ty = threadIdx.y;
#pragma unroll
    for (int r = 0; r < 4; r++) {
        int ii = i0 + ty + r * 8;
        int jj = j0 + tx;
        if (ii < NI) tile[ty + r * 8][tx] = g_Y[(ii * 2 + n) * NJ + jj];
    }
    __syncthreads();
#pragma unroll
    for (int r = 0; r < 4; r++) {
        int ii = i0 + tx;
        int jj = j0 + ty + r * 8;
        if (ii < NI) out[(n * NJ + jj) * NI + ii] = tile[tx][ty + r * 8];
    }
}

extern "C" void kernel_launch(void* const* d_in, const int* in_sizes, int n_in,
                              void* d_out, int out_size) {
    const float* X  = (const float*)d_in[0];
    const float* T0 = (const float*)d_in[1];
    const float* V0 = (const float*)d_in[2];

    dim3 b32(32, 8);
    k_init_tvw<<<209, 256>>>(T0, V0);
    k_init_x<<<dim3(33, 64, 2), b32>>>((const float2*)X);

    for (int it = 0; it < 5; it++) {
        k_nmf_t<<<NI, 256>>>(it == 0 ? 1 : 0);
        k_nmf_v_part<<<dim3(NJ / 256, NCH), 256>>>();
        k_nmf_v_red<<<NJ * 16 / 256, 256>>>();
        k_ip_y<<<NI, 256>>>();
    }

    k_out<<<dim3(33, 64, 2), b32>>>((float2*)d_out);
}

// round 16
// speedup vs baseline: 1.2857x; 1.0289x over previous
#include <cuda_runtime.h>

// ILRMA: M=N=2, I=1025 freq bins, J=2048 frames, K=8 bases, 5 iterations.
// Layouts (device globals):
//   X,Y : float2 [(i*2+m)*J + j]            (complex interleaved)
//   T   : g_T[n][i*8 + k]
//   V   : g_V[n][j*8 + k]                   (j-major, k contiguous -> float4 pairs)
//   YdR : g_YdR[n][i*J + j]
//   W   : g_W{r,i}[i*4 + n*2 + m]
//   partials: g_p{N,D}[(c*J + j)*16 + n*8 + k]
// R16: fuse nmf_t(it+1) into ip_y(it) => Y never round-trips through DRAM
// (except the final iteration, which writes Y for the output transpose).
// Loop: nmf_t(0, from X); 5x { v_part; v_red; ip_nmf(last?) }.

#define NI 1025
#define NJ 2048
#define NK 8
#define NMF_EPSF 1e-20f
#define IP_EPSF  1e-20f
#define NCH 55
#define ICHUNK 19
#define IJ  (NI*NJ)
#define IMJ (NI*2*NJ)

static __device__ float2 g_X[IMJ];
static __device__ float2 g_Y[IMJ];
static __device__ float  g_YdR[2][IJ];
static __device__ float  g_T[2][NI*NK];
static __device__ float  g_V[2][NJ*NK];
static __device__ float  g_Wr[NI*4];
static __device__ float  g_Wi[NI*4];
static __device__ float  g_pN[NCH*NJ*16];
static __device__ float  g_pD[NCH*NJ*16];

__device__ __forceinline__ float warp_sum(float v) {
#pragma unroll
    for (int o = 16; o > 0; o >>= 1) v += __shfl_down_sync(0xffffffffu, v, o);
    return v;
}

// ---------------------------------------------------------------------------
// Init: T/V de-interleave, W = identity
// ---------------------------------------------------------------------------
__global__ void k_init_tvw(const float* __restrict__ T0, const float* __restrict__ V0) {
    int idx = blockIdx.x * 256 + threadIdx.x;
    if (idx < 16400) {                       // T: (I,K,N) -> [n][i*8+k]
        int n = idx / 8200, r = idx % 8200;
        g_T[n][r] = T0[r * 2 + n];
    } else if (idx < 16400 + 32768) {        // V: (K,J,N) -> [n][j*8+k]
        int v = idx - 16400;
        int n = v / 16384, r = v % 16384;    // r = k*J + j
        int k = r / NJ, j = r % NJ;
        g_V[n][j * 8 + k] = V0[r * 2 + n];
    } else if (idx < 16400 + 32768 + 4100) { // W = eye(2) per i
        int w = idx - 49168;
        int q = w & 3;
        g_Wr[w] = ((q >> 1) == (q & 1)) ? 1.f : 0.f;
        g_Wi[w] = 0.f;
    }
}

// ---------------------------------------------------------------------------
// Init: transpose X (M,J,I,2) -> g_X[(i*2+m)*J+j]. (Y0 = X, never stored.)
// ---------------------------------------------------------------------------
__global__ void k_init_x(const float2* __restrict__ X) {
    __shared__ float2 tile[32][33];
    int m = blockIdx.z;
    int i0 = blockIdx.x * 32, j0 = blockIdx.y * 32;
    int tx = threadIdx.x, ty = threadIdx.y;
#pragma unroll
    for (int r = 0; r < 4; r++) {
        int jj = j0 + ty + r * 8;
        int ii = i0 + tx;
        if (ii < NI) tile[ty + r * 8][tx] = X[(m * NJ + jj) * NI + ii];
    }
    __syncthreads();
#pragma unroll
    for (int r = 0; r < 4; r++) {
        int ii = i0 + ty + r * 8;
        int jj = j0 + tx;
        if (ii < NI) g_X[(ii * 2 + m) * NJ + jj] = tile[tx][ty + r * 8];
    }
}

// ---------------------------------------------------------------------------
// NMF T-update for iteration 0 only (Y0 == X). One 256-thread block per i.
// ---------------------------------------------------------------------------
__global__ void __launch_bounds__(256) k_nmf_t0() {
    int i = blockIdx.x;
    int tid = threadIdx.x;
    __shared__ float sT[2][NK];
    if (tid < 16) sT[tid >> 3][tid & 7] = g_T[tid >> 3][i * NK + (tid & 7)];
    __syncthreads();

    float aN[2][NK], aD[2][NK];
#pragma unroll
    for (int n = 0; n < 2; n++)
#pragma unroll
        for (int k = 0; k < NK; k++) { aN[n][k] = 0.f; aD[n][k] = 0.f; }

    for (int j = tid; j < NJ; j += 256) {
#pragma unroll
        for (int n = 0; n < 2; n++) {
            float4 v0 = *(const float4*)&g_V[n][j * 8];
            float4 v1 = *(const float4*)&g_V[n][j * 8 + 4];
            float v[NK] = {v0.x, v0.y, v0.z, v0.w, v1.x, v1.y, v1.z, v1.w};
            float R = 0.f;
#pragma unroll
            for (int k = 0; k < NK; k++) R = fmaf(sT[n][k], v[k], R);
            float2 y = __ldcg(&g_X[(i * 2 + n) * NJ + j]);
            float p = y.x * y.x + y.y * y.y;
            float m = fabsf(R);
            float ydr = __fdividef(p, m * m + NMF_EPSF);
            float rd  = __fdividef(1.f, m + NMF_EPSF);
            __stcg(&g_YdR[n][i * NJ + j], ydr);
#pragma unroll
            for (int k = 0; k < NK; k++) {
                aN[n][k] = fmaf(ydr, v[k], aN[n][k]);
                aD[n][k] = fmaf(rd, v[k], aD[n][k]);
            }
        }
    }

    __shared__ float rbuf[8][32];
    int warp = tid >> 5, lane = tid & 31;
#pragma unroll
    for (int n = 0; n < 2; n++)
#pragma unroll
        for (int k = 0; k < NK; k++) {
            float sn = warp_sum(aN[n][k]);
            float sd = warp_sum(aD[n][k]);
            if (lane == 0) { rbuf[warp][n * 16 + k] = sn; rbuf[warp][n * 16 + 8 + k] = sd; }
        }
    __syncthreads();
    __shared__ float fin[32];
    if (tid < 32) {
        float s = 0.f;
#pragma unroll
        for (int w = 0; w < 8; w++) s += rbuf[w][tid];
        fin[tid] = s;
    }
    __syncthreads();
    if (tid < 16) {
        int n = tid >> 3, k = tid & 7;
        float num = fin[n * 16 + k], den = fin[n * 16 + 8 + k];
        g_T[n][i * NK + k] = sT[n][k] * sqrtf(__fdividef(num, den + NMF_EPSF));
    }
}

// ---------------------------------------------------------------------------
// NMF V-update partial sums. Grid (J/256, NCH) = 440 blocks (one full wave).
// YdR loads batched to registers (MLP=19). Out-of-range i contributes 0.
// ---------------------------------------------------------------------------
__global__ void __launch_bounds__(256) k_nmf_v_part() {
    int j = blockIdx.x * 256 + threadIdx.x;
    int c = blockIdx.y;
    int i0 = c * ICHUNK;
    int nvalid = NI - i0; if (nvalid > ICHUNK) nvalid = ICHUNK;

    __shared__ float sT[ICHUNK][16];
    for (int t = threadIdx.x; t < ICHUNK * 16; t += 256) {
        int ii = t >> 4, q = t & 15;
        sT[ii][q] = (ii < nvalid) ? g_T[q >> 3][(i0 + ii) * NK + (q & 7)] : 0.f;
    }
    __syncthreads();

    float aN[2][NK], aD[2][NK];
#pragma unroll
    for (int n = 0; n < 2; n++)
#pragma unroll
        for (int k = 0; k < NK; k++) { aN[n][k] = 0.f; aD[n][k] = 0.f; }

#pragma unroll
    for (int n = 0; n < 2; n++) {
        float4 v0 = *(const float4*)&g_V[n][j * 8];
        float4 v1 = *(const float4*)&g_V[n][j * 8 + 4];
        float v[NK] = {v0.x, v0.y, v0.z, v0.w, v1.x, v1.y, v1.z, v1.w};

        float ydr[ICHUNK];
        const float* base = &g_YdR[n][i0 * NJ + j];
#pragma unroll
        for (int li = 0; li < ICHUNK; li++)
            ydr[li] = (li < nvalid) ? __ldcg(base + li * NJ) : 0.f;

#pragma unroll
        for (int li = 0; li < ICHUNK; li++) {
            float R = 0.f;
#pragma unroll
            for (int k = 0; k < NK; k++) R = fmaf(sT[li][n * 8 + k], v[k], R);
            float rd2 = __fdividef(1.f, fabsf(R) + NMF_EPSF);
#pragma unroll
            for (int k = 0; k < NK; k++) {
                aN[n][k] = fmaf(sT[li][n * 8 + k], ydr[li], aN[n][k]);
                aD[n][k] = fmaf(sT[li][n * 8 + k], rd2, aD[n][k]);
            }
        }
    }

    int pbase = (c * NJ + j) * 16;
    *(float4*)&g_pN[pbase + 0]  = make_float4(aN[0][0], aN[0][1], aN[0][2], aN[0][3]);
    *(float4*)&g_pN[pbase + 4]  = make_float4(aN[0][4], aN[0][5], aN[0][6], aN[0][7]);
    *(float4*)&g_pN[pbase + 8]  = make_float4(aN[1][0], aN[1][1], aN[1][2], aN[1][3]);
    *(float4*)&g_pN[pbase + 12] = make_float4(aN[1][4], aN[1][5], aN[1][6], aN[1][7]);
    *(float4*)&g_pD[pbase + 0]  = make_float4(aD[0][0], aD[0][1], aD[0][2], aD[0][3]);
    *(float4*)&g_pD[pbase + 4]  = make_float4(aD[0][4], aD[0][5], aD[0][6], aD[0][7]);
    *(float4*)&g_pD[pbase + 8]  = make_float4(aD[1][0], aD[1][1], aD[1][2], aD[1][3]);
    *(float4*)&g_pD[pbase + 12] = make_float4(aD[1][4], aD[1][5], aD[1][6], aD[1][7]);
}

// ---------------------------------------------------------------------------
// NMF V-update reduce: one thread per (j, n, k); V *= sqrt(num/(den+eps))
// ---------------------------------------------------------------------------
__global__ void __launch_bounds__(256) k_nmf_v_red() {
    int idx = blockIdx.x * 256 + threadIdx.x;   // 32768 = J*16
    int j = idx >> 4, q = idx & 15;
    float sn = 0.f, sd = 0.f;
#pragma unroll 5
    for (int c = 0; c < NCH; c++) {
        sn += g_pN[(c * NJ + j) * 16 + q];
        sd += g_pD[(c * NJ + j) * 16 + q];
    }
    int n = q >> 3, k = q & 7;
    g_V[n][j * 8 + k] *= sqrtf(__fdividef(sn, sd + NMF_EPSF));
}

// ---------------------------------------------------------------------------
// Fused: IP update + (Y = W@Xc consumed in-place by the NEXT iteration's
// NMF T-update). One 256-thread block per i.
//   pass 1: weighted covariance from X (cached to smem), 2x2 IP solve -> W.
//   pass 2 (last==0): compute y on the fly from sW/sX, run nmf_t phase for
//                     iteration it+1 (store YdR, update T). No global Y.
//   pass 2 (last==1): write Y to global for the output transpose.
// ---------------------------------------------------------------------------
__global__ void __launch_bounds__(256) k_ip_nmf(int last) {
    int i = blockIdx.x;
    int tid = threadIdx.x;
    __shared__ float2 sX[2][NJ];
    __shared__ float sT[2][NK];
    __shared__ float sW[8];
    if (tid < 16) sT[tid >> 3][tid & 7] = g_T[tid >> 3][i * NK + (tid & 7)];
    __syncthreads();

    float acc[8]; // n*4 + {d00, d11, d01r, d01i}
#pragma unroll
    for (int q = 0; q < 8; q++) acc[q] = 0.f;

    for (int j = tid; j < NJ; j += 256) {
        float2 x0 = __ldcg(&g_X[(i * 2 + 0) * NJ + j]);
        float2 x1 = __ldcg(&g_X[(i * 2 + 1) * NJ + j]);
        sX[0][j] = x0; sX[1][j] = x1;
        float p0 = x0.x * x0.x + x0.y * x0.y;
        float p1 = x1.x * x1.x + x1.y * x1.y;
        float cr = x0.x * x1.x + x0.y * x1.y;
        float ci = x0.y * x1.x - x0.x * x1.y;
#pragma unroll
        for (int n = 0; n < 2; n++) {
            float4 v0 = *(const float4*)&g_V[n][j * 8];
            float4 v1 = *(const float4*)&g_V[n][j * 8 + 4];
            float R = sT[n][0] * v0.x + sT[n][1] * v0.y + sT[n][2] * v0.z + sT[n][3] * v0.w
                    + sT[n][4] * v1.x + sT[n][5] * v1.y + sT[n][6] * v1.z + sT[n][7] * v1.w;
            float w = __fdividef(1.f, R + IP_EPSF);
            acc[n * 4 + 0] = fmaf(w, p0, acc[n * 4 + 0]);
            acc[n * 4 + 1] = fmaf(w, p1, acc[n * 4 + 1]);
            acc[n * 4 + 2] = fmaf(w, cr, acc[n * 4 + 2]);
            acc[n * 4 + 3] = fmaf(w, ci, acc[n * 4 + 3]);
        }
    }

    __shared__ float rb[8][8];
    int warp = tid >> 5, lane = tid & 31;
#pragma unroll
    for (int q = 0; q < 8; q++) {
        float s = warp_sum(acc[q]);
        if (lane == 0) rb[warp][q] = s;
    }
    __syncthreads();
    __shared__ float sD[8];
    if (tid < 8) {
        float s = 0.f;
#pragma unroll
        for (int w = 0; w < 8; w++) s += rb[w][tid];
        sD[tid] = s;
    }
    __syncthreads();

    if (tid == 0) {
        float wr[2][2], wi[2][2];
#pragma unroll
        for (int q = 0; q < 4; q++) { wr[q >> 1][q & 1] = g_Wr[i * 4 + q]; wi[q >> 1][q & 1] = g_Wi[i * 4 + q]; }
        const float invJ = 1.f / (float)NJ;
#pragma unroll
        for (int n = 0; n < 2; n++) {
            float D00 = sD[n * 4 + 0] * invJ + IP_EPSF;
            float D11 = sD[n * 4 + 1] * invJ + IP_EPSF;
            float Dr  = sD[n * 4 + 2] * invJ;
            float Di  = sD[n * 4 + 3] * invJ;
            float A00r = wr[0][0] * D00 + wr[0][1] * Dr + wi[0][1] * Di;
            float A00i = wi[0][0] * D00 + wi[0][1] * Dr - wr[0][1] * Di;
            float A01r = wr[0][0] * Dr - wi[0][0] * Di + wr[0][1] * D11;
            float A01i = wi[0][0] * Dr + wr[0][0] * Di + wi[0][1] * D11;
            float A10r = wr[1][0] * D00 + wr[1][1] * Dr + wi[1][1] * Di;
            float A10i = wi[1][0] * D00 + wi[1][1] * Dr - wr[1][1] * Di;
            float A11r = wr[1][0] * Dr - wi[1][0] * Di + wr[1][1] * D11;
            float A11i = wi[1][0] * Dr + wr[1][0] * Di + wi[1][1] * D11;
            float detr = A00r * A11r - A00i * A11i - (A01r * A10r - A01i * A10i);
            float deti = A00r * A11i + A00i * A11r - (A01r * A10i + A01i * A10r);
            float nb0r, nb0i, nb1r, nb1i;
            if (n == 0) { nb0r = A11r; nb0i = A11i; nb1r = -A10r; nb1i = -A10i; }
            else        { nb0r = -A01r; nb0i = -A01i; nb1r = A00r; nb1i = A00i; }
            float inv = 1.f / (detr * detr + deti * deti);
            float b0r = (nb0r * detr + nb0i * deti) * inv;
            float b0i = (nb0i * detr - nb0r * deti) * inv;
            float b1r = (nb1r * detr + nb1i * deti) * inv;
            float b1i = (nb1i * detr - nb1r * deti) * inv;
            float Db0r = D00 * b0r + Dr * b1r - Di * b1i;
            float Db0i = D00 * b0i + Dr * b1i + Di * b1r;
            float Db1r = Dr * b0r + Di * b0i + D11 * b1r;
            float Db1i = Dr * b0i - Di * b0r + D11 * b1i;
            float e = b0r * Db0r + b0i * Db0i + b1r * Db1r + b1i * Db1i;
            float s = 1.f / sqrtf(e + IP_EPSF);
            wr[n][0] = b0r * s; wi[n][0] = -b0i * s;
            wr[n][1] = b1r * s; wi[n][1] = -b1i * s;
        }
#pragma unroll
        for (int q = 0; q < 4; q++) {
            g_Wr[i * 4 + q] = wr[q >> 1][q & 1];
            g_Wi[i * 4 + q] = wi[q >> 1][q & 1];
            sW[q] = wr[q >> 1][q & 1];
            sW[4 + q] = wi[q >> 1][q & 1];
        }
    }
    __syncthreads();

    float w00r = sW[0], w01r = sW[1], w10r = sW[2], w11r = sW[3];
    float w00i = sW[4], w01i = sW[5], w10i = sW[6], w11i = sW[7];

    if (last) {
        // Final iteration: materialize Y for the output transpose.
        for (int j = tid; j < NJ; j += 256) {
            float2 x0 = sX[0][j], x1 = sX[1][j];
            float2 y0, y1;
            y0.x = w00r * x0.x - w00i * x0.y + w01r * x1.x - w01i * x1.y;
            y0.y = w00r * x0.y + w00i * x0.x + w01r * x1.y + w01i * x1.x;
            y1.x = w10r * x0.x - w10i * x0.y + w11r * x1.x - w11i * x1.y;
            y1.y = w10r * x0.y + w10i * x0.x + w11r * x1.y + w11i * x1.x;
            __stcg(&g_Y[(i * 2 + 0) * NJ + j], y0);
            __stcg(&g_Y[(i * 2 + 1) * NJ + j], y1);
        }
        return;
    }

    // Not last: run nmf_t for iteration it+1 directly from smem (Y on the fly).
    float aN[2][NK], aD[2][NK];
#pragma unroll
    for (int n = 0; n < 2; n++)
#pragma unroll
        for (int k = 0; k < NK; k++) { aN[n][k] = 0.f; aD[n][k] = 0.f; }

    for (int j = tid; j < NJ; j += 256) {
        float2 x0 = sX[0][j], x1 = sX[1][j];
        float yr[2], yi[2];
        yr[0] = w00r * x0.x - w00i * x0.y + w01r * x1.x - w01i * x1.y;
        yi[0] = w00r * x0.y + w00i * x0.x + w01r * x1.y + w01i * x1.x;
        yr[1] = w10r * x0.x - w10i * x0.y + w11r * x1.x - w11i * x1.y;
        yi[1] = w10r * x0.y + w10i * x0.x + w11r * x1.y + w11i * x1.x;
#pragma unroll
        for (int n = 0; n < 2; n++) {
            float4 v0 = *(const float4*)&g_V[n][j * 8];
            float4 v1 = *(const float4*)&g_V[n][j * 8 + 4];
            float v[NK] = {v0.x, v0.y, v0.z, v0.w, v1.x, v1.y, v1.z, v1.w};
            float R = 0.f;
#pragma unroll
            for (int k = 0; k < NK; k++) R = fmaf(sT[n][k], v[k], R);
            float p = yr[n] * yr[n] + yi[n] * yi[n];
            float m = fabsf(R);
            float ydr = __fdividef(p, m * m + NMF_EPSF);
            float rd  = __fdividef(1.f, m + NMF_EPSF);
            __stcg(&g_YdR[n][i * NJ + j], ydr);
#pragma unroll
            for (int k = 0; k < NK; k++) {
                aN[n][k] = fmaf(ydr, v[k], aN[n][k]);
                aD[n][k] = fmaf(rd, v[k], aD[n][k]);
            }
        }
    }

    __shared__ float rbuf[8][32];
#pragma unroll
    for (int n = 0; n < 2; n++)
#pragma unroll
        for (int k = 0; k < NK; k++) {
            float sn = warp_sum(aN[n][k]);
            float sd = warp_sum(aD[n][k]);
            if (lane == 0) { rbuf[warp][n * 16 + k] = sn; rbuf[warp][n * 16 + 8 + k] = sd; }
        }
    __syncthreads();
    __shared__ float fin[32];
    if (tid < 32) {
        float s = 0.f;
#pragma unroll
        for (int w = 0; w < 8; w++) s += rbuf[w][tid];
        fin[tid] = s;
    }
    __syncthreads();
    if (tid < 16) {
        int n = tid >> 3, k = tid & 7;
        float num = fin[n * 16 + k], den = fin[n * 16 + 8 + k];
        g_T[n][i * NK + k] = sT[n][k] * sqrtf(__fdividef(num, den + NMF_EPSF));
    }
}

// ---------------------------------------------------------------------------
// Output: Y [i][n][j] -> out (N, J, I, 2), tiled i<->j transpose
// ---------------------------------------------------------------------------
__global__ void k_out(float2* __restrict__ out) {
    __shared__ float2 tile[32][33];
    int n = blockIdx.z;
    int i0 = blockIdx.x * 32, j0 = blockIdx.y * 32;
    int tx = threadIdx.x, ty = threadIdx.y;
#pragma unroll
    for (int r = 0; r < 4; r++) {
        int ii = i0 + ty + r * 8;
        int jj = j0 + tx;
        if (ii < NI) tile[ty + r * 8][tx] = g_Y[(ii * 2 + n) * NJ + jj];
    }
    __syncthreads();
#pragma unroll
    for (int r = 0; r < 4; r++) {
        int ii = i0 + tx;
        int jj = j0 + ty + r * 8;
        if (ii < NI) out[(n * NJ + jj) * NI + ii] = tile[tx][ty + r * 8];
    }
}

extern "C" void kernel_launch(void* const* d_in, const int* in_sizes, int n_in,
                              void* d_out, int out_size) {
    const float* X  = (const float*)d_in[0];
    const float* T0 = (const float*)d_in[1];
    const float* V0 = (const float*)d_in[2];

    dim3 b32(32, 8);
    k_init_tvw<<<209, 256>>>(T0, V0);
    k_init_x<<<dim3(33, 64, 2), b32>>>((const float2*)X);

    k_nmf_t0<<<NI, 256>>>();
    for (int it = 0; it < 5; it++) {
        k_nmf_v_part<<<dim3(NJ / 256, NCH), 256>>>();
        k_nmf_v_red<<<NJ * 16 / 256, 256>>>();
        k_ip_nmf<<<NI, 256>>>(it == 4 ? 1 : 0);
    }

    k_out<<<dim3(33, 64, 2), b32>>>((float2*)d_out);
}

// round 17
// speedup vs baseline: 1.3939x; 1.0841x over previous
#include <cuda_runtime.h>

// ILRMA: M=N=2, I=1025 freq bins, J=2048 frames, K=8 bases, 5 iterations.
// Layouts (device globals):
//   X   : float2 [(i*2+m)*J + j]            (complex interleaved)
//   T   : g_T[n][i*8 + k]
//   V   : g_V[n][j*8 + k]                   (j-major, k contiguous -> float4 pairs)
//   YdR : g_YdR[n][i*J + j]
//   W   : g_W{r,i}[i*4 + n*2 + m]
//   partials: g_p{N,D}[(c*J + j)*16 + n*8 + k]
// R17: (a) last ip_nmf stops after the W solve (no pass 2); g_Y is gone --
//      k_out computes Y = W@X during the output transpose (identical math).
//      (b) v_red unrolled x11 (MLP 22) -- its c-loop strides 128KB/step and
//      was DRAM-latency bound, same failure mode v_part had.

#define NI 1025
#define NJ 2048
#define NK 8
#define NMF_EPSF 1e-20f
#define IP_EPSF  1e-20f
#define NCH 55
#define ICHUNK 19
#define IJ  (NI*NJ)
#define IMJ (NI*2*NJ)

static __device__ float2 g_X[IMJ];
static __device__ float  g_YdR[2][IJ];
static __device__ float  g_T[2][NI*NK];
static __device__ float  g_V[2][NJ*NK];
static __device__ float  g_Wr[NI*4];
static __device__ float  g_Wi[NI*4];
static __device__ float  g_pN[NCH*NJ*16];
static __device__ float  g_pD[NCH*NJ*16];

__device__ __forceinline__ float warp_sum(float v) {
#pragma unroll
    for (int o = 16; o > 0; o >>= 1) v += __shfl_down_sync(0xffffffffu, v, o);
    return v;
}

// ---------------------------------------------------------------------------
// Init: T/V de-interleave, W = identity
// ---------------------------------------------------------------------------
__global__ void k_init_tvw(const float* __restrict__ T0, const float* __restrict__ V0) {
    int idx = blockIdx.x * 256 + threadIdx.x;
    if (idx < 16400) {                       // T: (I,K,N) -> [n][i*8+k]
        int n = idx / 8200, r = idx % 8200;
        g_T[n][r] = T0[r * 2 + n];
    } else if (idx < 16400 + 32768) {        // V: (K,J,N) -> [n][j*8+k]
        int v = idx - 16400;
        int n = v / 16384, r = v % 16384;    // r = k*J + j
        int k = r / NJ, j = r % NJ;
        g_V[n][j * 8 + k] = V0[r * 2 + n];
    } else if (idx < 16400 + 32768 + 4100) { // W = eye(2) per i
        int w = idx - 49168;
        int q = w & 3;
        g_Wr[w] = ((q >> 1) == (q & 1)) ? 1.f : 0.f;
        g_Wi[w] = 0.f;
    }
}

// ---------------------------------------------------------------------------
// Init: transpose X (M,J,I,2) -> g_X[(i*2+m)*J+j]. (Y0 = X, never stored.)
// ---------------------------------------------------------------------------
__global__ void k_init_x(const float2* __restrict__ X) {
    __shared__ float2 tile[32][33];
    int m = blockIdx.z;
    int i0 = blockIdx.x * 32, j0 = blockIdx.y * 32;
    int tx = threadIdx.x, ty = threadIdx.y;
#pragma unroll
    for (int r = 0; r < 4; r++) {
        int jj = j0 + ty + r * 8;
        int ii = i0 + tx;
        if (ii < NI) tile[ty + r * 8][tx] = X[(m * NJ + jj) * NI + ii];
    }
    __syncthreads();
#pragma unroll
    for (int r = 0; r < 4; r++) {
        int ii = i0 + ty + r * 8;
        int jj = j0 + tx;
        if (ii < NI) g_X[(ii * 2 + m) * NJ + jj] = tile[tx][ty + r * 8];
    }
}

// ---------------------------------------------------------------------------
// NMF T-update for iteration 0 only (Y0 == X). One 256-thread block per i.
// ---------------------------------------------------------------------------
__global__ void __launch_bounds__(256) k_nmf_t0() {
    int i = blockIdx.x;
    int tid = threadIdx.x;
    __shared__ float sT[2][NK];
    if (tid < 16) sT[tid >> 3][tid & 7] = g_T[tid >> 3][i * NK + (tid & 7)];
    __syncthreads();

    float aN[2][NK], aD[2][NK];
#pragma unroll
    for (int n = 0; n < 2; n++)
#pragma unroll
        for (int k = 0; k < NK; k++) { aN[n][k] = 0.f; aD[n][k] = 0.f; }

    for (int j = tid; j < NJ; j += 256) {
#pragma unroll
        for (int n = 0; n < 2; n++) {
            float4 v0 = *(const float4*)&g_V[n][j * 8];
            float4 v1 = *(const float4*)&g_V[n][j * 8 + 4];
            float v[NK] = {v0.x, v0.y, v0.z, v0.w, v1.x, v1.y, v1.z, v1.w};
            float R = 0.f;
#pragma unroll
            for (int k = 0; k < NK; k++) R = fmaf(sT[n][k], v[k], R);
            float2 y = __ldcg(&g_X[(i * 2 + n) * NJ + j]);
            float p = y.x * y.x + y.y * y.y;
            float m = fabsf(R);
            float ydr = __fdividef(p, m * m + NMF_EPSF);
            float rd  = __fdividef(1.f, m + NMF_EPSF);
            __stcg(&g_YdR[n][i * NJ + j], ydr);
#pragma unroll
            for (int k = 0; k < NK; k++) {
                aN[n][k] = fmaf(ydr, v[k], aN[n][k]);
                aD[n][k] = fmaf(rd, v[k], aD[n][k]);
            }
        }
    }

    __shared__ float rbuf[8][32];
    int warp = tid >> 5, lane = tid & 31;
#pragma unroll
    for (int n = 0; n < 2; n++)
#pragma unroll
        for (int k = 0; k < NK; k++) {
            float sn = warp_sum(aN[n][k]);
            float sd = warp_sum(aD[n][k]);
            if (lane == 0) { rbuf[warp][n * 16 + k] = sn; rbuf[warp][n * 16 + 8 + k] = sd; }
        }
    __syncthreads();
    __shared__ float fin[32];
    if (tid < 32) {
        float s = 0.f;
#pragma unroll
        for (int w = 0; w < 8; w++) s += rbuf[w][tid];
        fin[tid] = s;
    }
    __syncthreads();
    if (tid < 16) {
        int n = tid >> 3, k = tid & 7;
        float num = fin[n * 16 + k], den = fin[n * 16 + 8 + k];
        g_T[n][i * NK + k] = sT[n][k] * sqrtf(__fdividef(num, den + NMF_EPSF));
    }
}

// ---------------------------------------------------------------------------
// NMF V-update partial sums. Grid (J/256, NCH) = 440 blocks (one full wave).
// YdR loads batched to registers (MLP=19). Out-of-range i contributes 0.
// ---------------------------------------------------------------------------
__global__ void __launch_bounds__(256) k_nmf_v_part() {
    int j = blockIdx.x * 256 + threadIdx.x;
    int c = blockIdx.y;
    int i0 = c * ICHUNK;
    int nvalid = NI - i0; if (nvalid > ICHUNK) nvalid = ICHUNK;

    __shared__ float sT[ICHUNK][16];
    for (int t = threadIdx.x; t < ICHUNK * 16; t += 256) {
        int ii = t >> 4, q = t & 15;
        sT[ii][q] = (ii < nvalid) ? g_T[q >> 3][(i0 + ii) * NK + (q & 7)] : 0.f;
    }
    __syncthreads();

    float aN[2][NK], aD[2][NK];
#pragma unroll
    for (int n = 0; n < 2; n++)
#pragma unroll
        for (int k = 0; k < NK; k++) { aN[n][k] = 0.f; aD[n][k] = 0.f; }

#pragma unroll
    for (int n = 0; n < 2; n++) {
        float4 v0 = *(const float4*)&g_V[n][j * 8];
        float4 v1 = *(const float4*)&g_V[n][j * 8 + 4];
        float v[NK] = {v0.x, v0.y, v0.z, v0.w, v1.x, v1.y, v1.z, v1.w};

        float ydr[ICHUNK];
        const float* base = &g_YdR[n][i0 * NJ + j];
#pragma unroll
        for (int li = 0; li < ICHUNK; li++)
            ydr[li] = (li < nvalid) ? __ldcg(base + li * NJ) : 0.f;

#pragma unroll
        for (int li = 0; li < ICHUNK; li++) {
            float R = 0.f;
#pragma unroll
            for (int k = 0; k < NK; k++) R = fmaf(sT[li][n * 8 + k], v[k], R);
            float rd2 = __fdividef(1.f, fabsf(R) + NMF_EPSF);
#pragma unroll
            for (int k = 0; k < NK; k++) {
                aN[n][k] = fmaf(sT[li][n * 8 + k], ydr[li], aN[n][k]);
                aD[n][k] = fmaf(sT[li][n * 8 + k], rd2, aD[n][k]);
            }
        }
    }

    int pbase = (c * NJ + j) * 16;
    *(float4*)&g_pN[pbase + 0]  = make_float4(aN[0][0], aN[0][1], aN[0][2], aN[0][3]);
    *(float4*)&g_pN[pbase + 4]  = make_float4(aN[0][4], aN[0][5], aN[0][6], aN[0][7]);
    *(float4*)&g_pN[pbase + 8]  = make_float4(aN[1][0], aN[1][1], aN[1][2], aN[1][3]);
    *(float4*)&g_pN[pbase + 12] = make_float4(aN[1][4], aN[1][5], aN[1][6], aN[1][7]);
    *(float4*)&g_pD[pbase + 0]  = make_float4(aD[0][0], aD[0][1], aD[0][2], aD[0][3]);
    *(float4*)&g_pD[pbase + 4]  = make_float4(aD[0][4], aD[0][5], aD[0][6], aD[0][7]);
    *(float4*)&g_pD[pbase + 8]  = make_float4(aD[1][0], aD[1][1], aD[1][2], aD[1][3]);
    *(float4*)&g_pD[pbase + 12] = make_float4(aD[1][4], aD[1][5], aD[1][6], aD[1][7]);
}

// ---------------------------------------------------------------------------
// NMF V-update reduce: one thread per (j, n, k); V *= sqrt(num/(den+eps)).
// c-loop strides 128KB -> DRAM-latency bound; unroll 11 (55 = 5*11) for MLP.
// ---------------------------------------------------------------------------
__global__ void __launch_bounds__(256) k_nmf_v_red() {
    int idx = blockIdx.x * 256 + threadIdx.x;   // 32768 = J*16
    int j = idx >> 4, q = idx & 15;
    float sn = 0.f, sd = 0.f;
#pragma unroll 11
    for (int c = 0; c < NCH; c++) {
        sn += g_pN[(c * NJ + j) * 16 + q];
        sd += g_pD[(c * NJ + j) * 16 + q];
    }
    int n = q >> 3, k = q & 7;
    g_V[n][j * 8 + k] *= sqrtf(__fdividef(sn, sd + NMF_EPSF));
}

// ---------------------------------------------------------------------------
// Fused: IP update + the NEXT iteration's NMF T-update (Y on the fly).
// One 256-thread block per i.
//   pass 1: weighted covariance from X (cached to smem), 2x2 IP solve -> W.
//   last==0: pass 2 computes y from sW/sX, stores YdR, updates T.
//   last==1: returns right after the W solve (k_out regenerates Y itself).
// ---------------------------------------------------------------------------
__global__ void __launch_bounds__(256) k_ip_nmf(int last) {
    int i = blockIdx.x;
    int tid = threadIdx.x;
    __shared__ float2 sX[2][NJ];
    __shared__ float sT[2][NK];
    __shared__ float sW[8];
    if (tid < 16) sT[tid >> 3][tid & 7] = g_T[tid >> 3][i * NK + (tid & 7)];
    __syncthreads();

    float acc[8]; // n*4 + {d00, d11, d01r, d01i}
#pragma unroll
    for (int q = 0; q < 8; q++) acc[q] = 0.f;

    for (int j = tid; j < NJ; j += 256) {
        float2 x0 = __ldcg(&g_X[(i * 2 + 0) * NJ + j]);
        float2 x1 = __ldcg(&g_X[(i * 2 + 1) * NJ + j]);
        sX[0][j] = x0; sX[1][j] = x1;
        float p0 = x0.x * x0.x + x0.y * x0.y;
        float p1 = x1.x * x1.x + x1.y * x1.y;
        float cr = x0.x * x1.x + x0.y * x1.y;
        float ci = x0.y * x1.x - x0.x * x1.y;
#pragma unroll
        for (int n = 0; n < 2; n++) {
            float4 v0 = *(const float4*)&g_V[n][j * 8];
            float4 v1 = *(const float4*)&g_V[n][j * 8 + 4];
            float R = sT[n][0] * v0.x + sT[n][1] * v0.y + sT[n][2] * v0.z + sT[n][3] * v0.w
                    + sT[n][4] * v1.x + sT[n][5] * v1.y + sT[n][6] * v1.z + sT[n][7] * v1.w;
            float w = __fdividef(1.f, R + IP_EPSF);
            acc[n * 4 + 0] = fmaf(w, p0, acc[n * 4 + 0]);
            acc[n * 4 + 1] = fmaf(w, p1, acc[n * 4 + 1]);
            acc[n * 4 + 2] = fmaf(w, cr, acc[n * 4 + 2]);
            acc[n * 4 + 3] = fmaf(w, ci, acc[n * 4 + 3]);
        }
    }

    __shared__ float rb[8][8];
    int warp = tid >> 5, lane = tid & 31;
#pragma unroll
    for (int q = 0; q < 8; q++) {
        float s = warp_sum(acc[q]);
        if (lane == 0) rb[warp][q] = s;
    }
    __syncthreads();
    __shared__ float sD[8];
    if (tid < 8) {
        float s = 0.f;
#pragma unroll
        for (int w = 0; w < 8; w++) s += rb[w][tid];
        sD[tid] = s;
    }
    __syncthreads();

    if (tid == 0) {
        float wr[2][2], wi[2][2];
#pragma unroll
        for (int q = 0; q < 4; q++) { wr[q >> 1][q & 1] = g_Wr[i * 4 + q]; wi[q >> 1][q & 1] = g_Wi[i * 4 + q]; }
        const float invJ = 1.f / (float)NJ;
#pragma unroll
        for (int n = 0; n < 2; n++) {
            float D00 = sD[n * 4 + 0] * invJ + IP_EPSF;
            float D11 = sD[n * 4 + 1] * invJ + IP_EPSF;
            float Dr  = sD[n * 4 + 2] * invJ;
            float Di  = sD[n * 4 + 3] * invJ;
            float A00r = wr[0][0] * D00 + wr[0][1] * Dr + wi[0][1] * Di;
            float A00i = wi[0][0] * D00 + wi[0][1] * Dr - wr[0][1] * Di;
            float A01r = wr[0][0] * Dr - wi[0][0] * Di + wr[0][1] * D11;
            float A01i = wi[0][0] * Dr + wr[0][0] * Di + wi[0][1] * D11;
            float A10r = wr[1][0] * D00 + wr[1][1] * Dr + wi[1][1] * Di;
            float A10i = wi[1][0] * D00 + wi[1][1] * Dr - wr[1][1] * Di;
            float A11r = wr[1][0] * Dr - wi[1][0] * Di + wr[1][1] * D11;
            float A11i = wi[1][0] * Dr + wr[1][0] * Di + wi[1][1] * D11;
            float detr = A00r * A11r - A00i * A11i - (A01r * A10r - A01i * A10i);
            float deti = A00r * A11i + A00i * A11r - (A01r * A10i + A01i * A10r);
            float nb0r, nb0i, nb1r, nb1i;
            if (n == 0) { nb0r = A11r; nb0i = A11i; nb1r = -A10r; nb1i = -A10i; }
            else        { nb0r = -A01r; nb0i = -A01i; nb1r = A00r; nb1i = A00i; }
            float inv = 1.f / (detr * detr + deti * deti);
            float b0r = (nb0r * detr + nb0i * deti) * inv;
            float b0i = (nb0i * detr - nb0r * deti) * inv;
            float b1r = (nb1r * detr + nb1i * deti) * inv;
            float b1i = (nb1i * detr - nb1r * deti) * inv;
            float Db0r = D00 * b0r + Dr * b1r - Di * b1i;
            float Db0i = D00 * b0i + Dr * b1i + Di * b1r;
            float Db1r = Dr * b0r + Di * b0i + D11 * b1r;
            float Db1i = Dr * b0i - Di * b0r + D11 * b1i;
            float e = b0r * Db0r + b0i * Db0i + b1r * Db1r + b1i * Db1i;
            float s = 1.f / sqrtf(e + IP_EPSF);
            wr[n][0] = b0r * s; wi[n][0] = -b0i * s;
            wr[n][1] = b1r * s; wi[n][1] = -b1i * s;
        }
#pragma unroll
        for (int q = 0; q < 4; q++) {
            g_Wr[i * 4 + q] = wr[q >> 1][q & 1];
            g_Wi[i * 4 + q] = wi[q >> 1][q & 1];
            sW[q] = wr[q >> 1][q & 1];
            sW[4 + q] = wi[q >> 1][q & 1];
        }
    }
    __syncthreads();

    if (last) return;   // k_out recomputes Y = W@X itself

    float w00r = sW[0], w01r = sW[1], w10r = sW[2], w11r = sW[3];
    float w00i = sW[4], w01i = sW[5], w10i = sW[6], w11i = sW[7];

    // nmf_t for iteration it+1 directly from smem (Y on the fly).
    float aN[2][NK], aD[2][NK];
#pragma unroll
    for (int n = 0; n < 2; n++)
#pragma unroll
        for (int k = 0; k < NK; k++) { aN[n][k] = 0.f; aD[n][k] = 0.f; }

    for (int j = tid; j < NJ; j += 256) {
        float2 x0 = sX[0][j], x1 = sX[1][j];
        float yr[2], yi[2];
        yr[0] = w00r * x0.x - w00i * x0.y + w01r * x1.x - w01i * x1.y;
        yi[0] = w00r * x0.y + w00i * x0.x + w01r * x1.y + w01i * x1.x;
        yr[1] = w10r * x0.x - w10i * x0.y + w11r * x1.x - w11i * x1.y;
        yi[1] = w10r * x0.y + w10i * x0.x + w11r * x1.y + w11i * x1.x;
#pragma unroll
        for (int n = 0; n < 2; n++) {
            float4 v0 = *(const float4*)&g_V[n][j * 8];
            float4 v1 = *(const float4*)&g_V[n][j * 8 + 4];
            float v[NK] = {v0.x, v0.y, v0.z, v0.w, v1.x, v1.y, v1.z, v1.w};
            float R = 0.f;
#pragma unroll
            for (int k = 0; k < NK; k++) R = fmaf(sT[n][k], v[k], R);
            float p = yr[n] * yr[n] + yi[n] * yi[n];
            float m = fabsf(R);
            float ydr = __fdividef(p, m * m + NMF_EPSF);
            float rd  = __fdividef(1.f, m + NMF_EPSF);
            __stcg(&g_YdR[n][i * NJ + j], ydr);
#pragma unroll
            for (int k = 0; k < NK; k++) {
                aN[n][k] = fmaf(ydr, v[k], aN[n][k]);
                aD[n][k] = fmaf(rd, v[k], aD[n][k]);
            }
        }
    }

    __shared__ float rbuf[8][32];
#pragma unroll
    for (int n = 0; n < 2; n++)
#pragma unroll
        for (int k = 0; k < NK; k++) {
            float sn = warp_sum(aN[n][k]);
            float sd = warp_sum(aD[n][k]);
            if (lane == 0) { rbuf[warp][n * 16 + k] = sn; rbuf[warp][n * 16 + 8 + k] = sd; }
        }
    __syncthreads();
    __shared__ float fin[32];
    if (tid < 32) {
        float s = 0.f;
#pragma unroll
        for (int w = 0; w < 8; w++) s += rbuf[w][tid];
        fin[tid] = s;
    }
    __syncthreads();
    if (tid < 16) {
        int n = tid >> 3, k = tid & 7;
        float num = fin[n * 16 + k], den = fin[n * 16 + 8 + k];
        g_T[n][i * NK + k] = sT[n][k] * sqrtf(__fdividef(num, den + NMF_EPSF));
    }
}

// ---------------------------------------------------------------------------
// Output: compute Y = W@X on the fly and transpose [i][j] -> (N, J, I, 2).
// ---------------------------------------------------------------------------
__global__ void k_out(float2* __restrict__ out) {
    __shared__ float2 tile[32][33];
    __shared__ float sW[32][4];   // [ii][{wr0, wi0, wr1, wi1}] for this n
    int n = blockIdx.z;
    int i0 = blockIdx.x * 32, j0 = blockIdx.y * 32;
    int tx = threadIdx.x, ty = threadIdx.y;
    int tid = ty * 32 + tx;

    if (tid < 128) {
        int ii = tid >> 2, q = tid & 3;
        int gi = i0 + ii;
        if (gi < NI) {
            int m = q >> 1;
            sW[ii][q] = (q & 1) ? g_Wi[gi * 4 + n * 2 + m] : g_Wr[gi * 4 + n * 2 + m];
        }
    }
    __syncthreads();

#pragma unroll
    for (int r = 0; r < 4; r++) {
        int li = ty + r * 8;
        int ii = i0 + li;
        int jj = j0 + tx;
        if (ii < NI) {
            float2 x0 = g_X[(ii * 2 + 0) * NJ + jj];
            float2 x1 = g_X[(ii * 2 + 1) * NJ + jj];
            float wr0 = sW[li][0], wi0 = sW[li][1], wr1 = sW[li][2], wi1 = sW[li][3];
            float2 y;
            y.x = wr0 * x0.x - wi0 * x0.y + wr1 * x1.x - wi1 * x1.y;
            y.y = wr0 * x0.y + wi0 * x0.x + wr1 * x1.y + wi1 * x1.x;
            tile[li][tx] = y;
        }
    }
    __syncthreads();
#pragma unroll
    for (int r = 0; r < 4; r++) {
        int ii = i0 + tx;
        int jj = j0 + ty + r * 8;
        if (ii < NI) out[(n * NJ + jj) * NI + ii] = tile[tx][ty + r * 8];
    }
}

extern "C" void kernel_launch(void* const* d_in, const int* in_sizes, int n_in,
                              void* d_out, int out_size) {
    const float* X  = (const float*)d_in[0];
    const float* T0 = (const float*)d_in[1];
    const float* V0 = (const float*)d_in[2];

    dim3 b32(32, 8);
    k_init_tvw<<<209, 256>>>(T0, V0);
    k_init_x<<<dim3(33, 64, 2), b32>>>((const float2*)X);

    k_nmf_t0<<<NI, 256>>>();
    for (int it = 0; it < 5; it++) {
        k_nmf_v_part<<<dim3(NJ / 256, NCH), 256>>>();
        k_nmf_v_red<<<NJ * 16 / 256, 256>>>();
        k_ip_nmf<<<NI, 256>>>(it == 4 ? 1 : 0);
    }

    k_out<<<dim3(33, 64, 2), b32>>>((float2*)d_out);
}